// round 10
// baseline (speedup 1.0000x reference)
#include <cuda_runtime.h>
#include <cstdint>

#define NPTS 4096
#define NTH  1024

// d_out float32 layout:
//   Pc [4][2][4096][3] @0, Tc @98304, keepP @196608, keepT @229376,
//   tp @262144, fp @294912, fn @327680
#define OFF_TC 98304
#define OFF_KP 196608
#define OFF_KT 229376
#define OFF_TP 262144
#define OFF_FP 294912
#define OFF_FN 327680

#define NBX 32
#define NBZ 8
#define CAP 12
#define NNCAP 16
#define MAXV 2048

__device__ unsigned long long g_run0[16 * 4096];
__device__ unsigned long long g_run1[16 * 4096];
// per-half compacted valid points (sorted order preserved)
__device__ float g_vx[16 * 4096];
__device__ float g_vy[16 * 4096];
__device__ float g_vz[16 * 4096];
__device__ unsigned short g_vs[16 * 4096];
__device__ int g_vcnt[32];
// NMS-kept compact lists per problem
__device__ float g_kx[16 * 2048];
__device__ float g_ky[16 * 2048];
__device__ float g_kz[16 * 2048];
__device__ unsigned short g_kpos[16 * 2048];
__device__ int g_kcnt[16];

__device__ __forceinline__ float dist2(float ax, float ay, float az,
                                       float bx, float by, float bz) {
    float dx = __fadd_rn(ax, -bx);
    float dy = __fadd_rn(ay, -by);
    float dz = __fadd_rn(az, -bz);
    return __fadd_rn(__fadd_rn(__fmul_rn(dx, dx), __fmul_rn(dy, dy)),
                     __fmul_rn(dz, dz));
}

__device__ __forceinline__ int clampi(int v, int lo, int hi) {
    return v < lo ? lo : (v > hi ? hi : v);
}

__device__ __forceinline__ void binCoords(float x, float y, float z,
                                          float invXY, float invZ,
                                          int& bx, int& by, int& bz) {
    bx = clampi((int)floorf(__fmul_rn(__fadd_rn(x, 4.5f), invXY)), 0, NBX - 1);
    by = clampi((int)floorf(__fmul_rn(__fadd_rn(y, 4.5f), invXY)), 0, NBX - 1);
    bz = clampi((int)floorf(__fmul_rn(__fadd_rn(z, 4.0f), invZ)),  0, NBZ - 1);
}

__device__ __forceinline__ int blockScanExcl(int cnt, int* wsum, int tid) {
    int lane = tid & 31, wid = tid >> 5;
    int v = cnt;
    for (int o = 1; o < 32; o <<= 1) {
        int nn = __shfl_up_sync(0xFFFFFFFFu, v, o);
        if (lane >= o) v += nn;
    }
    if (lane == 31) wsum[wid] = v;
    __syncthreads();
    if (wid == 0) {
        int w = wsum[lane];
        for (int o = 1; o < 32; o <<= 1) {
            int nn = __shfl_up_sync(0xFFFFFFFFu, w, o);
            if (lane >= o) w += nn;
        }
        wsum[lane] = w;
    }
    __syncthreads();
    return v - cnt + (wid ? wsum[wid - 1] : 0);
}

// ---------------------------------------------------------------------------
// Kernel A (64 blocks): sort 1024-key runs -> g_run0
// ---------------------------------------------------------------------------
__global__ void __launch_bounds__(1024) k_sortA(const float* __restrict__ pred,
                                                const float* __restrict__ targ)
{
    extern __shared__ unsigned char sm[];
    unsigned long long* s = (unsigned long long*)sm;   // [1024]
    const int tid = threadIdx.x;
    const int bi = blockIdx.x;
    const int prob = bi >> 2;
    const int quarter = bi & 3;
    const int t = prob >> 3;
    const int be = prob & 7;
    const int b = be >> 1;
    const int e = be & 1;
    const float* in = (t == 0) ? pred : targ;

    int n = quarter * 1024 + tid;
    int z = n >> 10, x = (n >> 5) & 31, y = n & 31;
    int base = ((((b * 32 + x) * 32 + y) * 4 + z) * 8) + e * 4;
    float conf = in[base + 3];
    unsigned u = __float_as_uint(conf);
    u = (u & 0x80000000u) ? ~u : (u | 0x80000000u);
    unsigned long long v = (((unsigned long long)(~u)) << 32) | (unsigned)n;

    for (int k = 2; k <= 1024; k <<= 1) {
        bool up = ((tid & k) == 0);
        for (int j = k >> 1; j > 0; j >>= 1) {
            unsigned long long p;
            if (j >= 32) {
                s[tid] = v;
                __syncthreads();
                p = s[tid ^ j];
                __syncthreads();
            } else {
                p = __shfl_xor_sync(0xFFFFFFFFu, v, j);
            }
            bool lower = ((tid & j) == 0);
            bool kmin = (lower == up);
            unsigned long long mn = v < p ? v : p;
            unsigned long long mx = v < p ? p : v;
            v = kmin ? mn : mx;
        }
    }
    g_run0[prob * 4096 + quarter * 1024 + tid] = v;
}

// ---------------------------------------------------------------------------
// Kernel B (32 blocks): merge 1024+1024 -> 2048 -> g_run1
// ---------------------------------------------------------------------------
__global__ void __launch_bounds__(1024) k_sortB()
{
    extern __shared__ unsigned char sm[];
    unsigned long long* sA = (unsigned long long*)sm;              // [1024]
    unsigned long long* sB = (unsigned long long*)(sm + 8 * 1024); // [1024]
    const int tid = threadIdx.x;
    const int prob = blockIdx.x >> 1;
    const int half = blockIdx.x & 1;
    const unsigned long long* src = g_run0 + prob * 4096 + half * 2048;
    sA[tid] = src[tid];
    sB[tid] = src[1024 + tid];
    __syncthreads();

    int diag = tid * 2;
    int lo = diag > 1024 ? diag - 1024 : 0;
    int hi = diag < 1024 ? diag : 1024;
    while (lo < hi) {
        int mid = (lo + hi) >> 1;
        if (sA[mid] < sB[diag - 1 - mid]) lo = mid + 1; else hi = mid;
    }
    int ai = lo, bj = diag - lo;
    unsigned long long* dst = g_run1 + prob * 4096 + half * 2048;
    #pragma unroll
    for (int r = 0; r < 2; r++) {
        bool takeA = (bj >= 1024) || (ai < 1024 && sA[ai] <= sB[bj]);
        dst[diag + r] = takeA ? sA[ai++] : sB[bj++];
    }
}

// ---------------------------------------------------------------------------
// Kernel C1 (32 blocks, 2/problem): merge-path half -> coords -> Pc/Tc
//   + per-half order-preserving valid compaction -> g_v*
// ---------------------------------------------------------------------------
__global__ void __launch_bounds__(1024) k_coords(const float* __restrict__ pred,
                                                 const float* __restrict__ targ,
                                                 float* __restrict__ out)
{
    extern __shared__ unsigned char sm[];
    unsigned long long* sA2 = (unsigned long long*)sm;             // [2048] 16KB
    unsigned long long* sB2 = (unsigned long long*)(sm + 16 * 1024);
    __shared__ int wsum[32];

    const int tid = threadIdx.x;
    const int bi = blockIdx.x;
    const int prob = bi >> 1;
    const int half = bi & 1;
    const int t = prob >> 3;
    const int be = prob & 7;
    const int b = be >> 1;
    const int e = be & 1;
    const float* in = (t == 0) ? pred : targ;

    {
        const unsigned long long* src = g_run1 + prob * 4096;
        sA2[tid] = src[tid];
        sA2[1024 + tid] = src[1024 + tid];
        sB2[tid] = src[2048 + tid];
        sB2[1024 + tid] = src[3072 + tid];
    }
    __syncthreads();

    const int diag = half * 2048 + tid * 2;
    int lo = diag > 2048 ? diag - 2048 : 0;
    int hi = diag < 2048 ? diag : 2048;
    while (lo < hi) {
        int mid = (lo + hi) >> 1;
        if (sA2[mid] < sB2[diag - 1 - mid]) lo = mid + 1; else hi = mid;
    }
    int ai = lo, bj = diag - lo;
    unsigned long long myk[2];
    #pragma unroll
    for (int r = 0; r < 2; r++) {
        bool takeA = (bj >= 2048) || (ai < 2048 && sA2[ai] <= sB2[bj]);
        myk[r] = takeA ? sA2[ai++] : sB2[bj++];
    }

    float rx[2], ry[2], rz[2];
    int vf[2]; int cnt = 0;
    #pragma unroll
    for (int q = 0; q < 2; q++) {
        int n = (int)(myk[q] & 0xFFFFFFFFull);
        int z = n >> 10, x = (n >> 5) & 31, y = n & 31;
        int base = ((((b * 32 + x) * 32 + y) * 4 + z) * 8) + e * 4;
        float4 vv = *(const float4*)(in + base);
        float c0 = __fmul_rn(__fadd_rn(vv.z, (float)z), 0.75f);
        float c1 = __fmul_rn(__fadd_rn(vv.x, (float)x), 0.78125f);
        float c2 = __fmul_rn(__fadd_rn(vv.y, (float)y), 0.78125f);
        rx[q] = c0; ry[q] = c1; rz[q] = c2;
        vf[q] = (vv.w > 0.5f) ? 1 : 0;
        cnt += vf[q];
        int s = diag + q;
        int ob = (t ? OFF_TC : 0) + ((b * 2 + e) * 4096 + s) * 3;
        out[ob + 0] = c0; out[ob + 1] = c1; out[ob + 2] = c2;
    }

    int excl = blockScanExcl(cnt, wsum, tid);
    int gb = prob * 4096 + half * 2048;
    #pragma unroll
    for (int q = 0; q < 2; q++) {
        if (vf[q]) {
            g_vx[gb + excl] = rx[q];
            g_vy[gb + excl] = ry[q];
            g_vz[gb + excl] = rz[q];
            g_vs[gb + excl] = (unsigned short)(diag + q);
            excl++;
        }
    }
    if (tid == 0) g_vcnt[bi] = wsum[31];
}

// ---------------------------------------------------------------------------
// Kernel C2 (16 blocks): stitch -> bins -> neighbor lists -> chunked NMS
//   with SPARSE nonzero-row sweep (exact sequential semantics)
// ---------------------------------------------------------------------------
__global__ void __launch_bounds__(1024) k_nms2(float* __restrict__ out)
{
    extern __shared__ unsigned char sm[];
    float* cx = (float*)sm;                                      // 8KB
    float* cy = (float*)(sm + 8 * 1024);
    float* cz = (float*)(sm + 16 * 1024);
    unsigned short* spos = (unsigned short*)(sm + 24 * 1024);    // 4KB
    unsigned char* fullk = (unsigned char*)(sm + 28 * 1024);     // 4KB
    unsigned short* nbr = (unsigned short*)(sm + 32 * 1024);     // 64KB
    unsigned int* binCnt = (unsigned int*)(sm + 96 * 1024);      // 32KB
    unsigned int* binStart = (unsigned int*)(sm + 128 * 1024);   // 32KB
    unsigned short* binPts = (unsigned short*)(sm + 160 * 1024); // 4KB
    unsigned char* nbrCnt = (unsigned char*)(sm + 164 * 1024);   // 2KB
    unsigned char* state = (unsigned char*)(sm + 166 * 1024);    // 2KB (final keep flag)

    __shared__ int wsum[32];
    __shared__ unsigned long long matS[64];
    __shared__ unsigned long long supp;
    __shared__ unsigned long long nzmask;

    const int tid = threadIdx.x;
    const int prob = blockIdx.x;
    const int t = prob >> 3;
    const int be = prob & 7;
    const int b = be >> 1;
    const int e = be & 1;
    const float de = (e == 0) ? (float)(0.74 * 1.4) : (float)(0.528 * 1.4);
    const float dd = __fmul_rn(de, de);
    const float cellXY = fmaxf(de, 1.02f);
    const float invXY = 1.0f / cellXY;
    const float invZ = 1.0f / 1.3125f;

    const int c0 = min(g_vcnt[prob * 2], MAXV);
    const int c1 = g_vcnt[prob * 2 + 1];
    const int m = min(c0 + c1, MAXV);
    const int gb = prob * 4096;

    // stitch halves (order-preserving)
    for (int i = tid; i < c0; i += NTH) {
        cx[i] = g_vx[gb + i]; cy[i] = g_vy[gb + i]; cz[i] = g_vz[gb + i];
        spos[i] = g_vs[gb + i];
    }
    for (int i = tid; i < m - c0; i += NTH) {
        cx[c0 + i] = g_vx[gb + 2048 + i];
        cy[c0 + i] = g_vy[gb + 2048 + i];
        cz[c0 + i] = g_vz[gb + 2048 + i];
        spos[c0 + i] = g_vs[gb + 2048 + i];
    }
    for (int i = tid; i < NBX * NBX * NBZ; i += NTH) binCnt[i] = 0;
    for (int q = 0; q < 4; q++) fullk[tid * 4 + q] = 0;
    __syncthreads();

    // ---- bins ----
    for (int ci = tid; ci < m; ci += NTH) {
        int bx, by, bz;
        binCoords(cx[ci], cy[ci], cz[ci], invXY, invZ, bx, by, bz);
        atomicAdd(&binCnt[(bz * NBX + by) * NBX + bx], 1u);
    }
    __syncthreads();
    {
        int base8 = tid * 8;
        int loc[8]; int s = 0;
        for (int k2 = 0; k2 < 8; k2++) { loc[k2] = s; s += (int)binCnt[base8 + k2]; }
        int ex = blockScanExcl(s, wsum, tid);
        for (int k2 = 0; k2 < 8; k2++) binStart[base8 + k2] = (unsigned)(ex + loc[k2]);
    }
    __syncthreads();
    for (int i = tid; i < NBX * NBX * NBZ; i += NTH) binCnt[i] = 0;
    __syncthreads();
    for (int ci = tid; ci < m; ci += NTH) {
        int bx, by, bz;
        binCoords(cx[ci], cy[ci], cz[ci], invXY, invZ, bx, by, bz);
        int bb = (bz * NBX + by) * NBX + bx;
        unsigned off = atomicAdd(&binCnt[bb], 1u);
        binPts[binStart[bb] + off] = (unsigned short)ci;
    }
    __syncthreads();

    // ---- one-pass earlier-neighbor lists ----
    for (int ci = tid; ci < m; ci += NTH) {
        float px = cx[ci], py = cy[ci], pz = cz[ci];
        int bx, by, bz;
        binCoords(px, py, pz, invXY, invZ, bx, by, bz);
        int nc = 0;
        #pragma unroll
        for (int dzb = -1; dzb <= 1; dzb++) {
            int Z = bz + dzb;
            if (Z < 0 || Z >= NBZ) continue;
            #pragma unroll
            for (int dyb = -1; dyb <= 1; dyb++) {
                int Y = by + dyb;
                if (Y < 0 || Y >= NBX) continue;
                #pragma unroll
                for (int dxb = -1; dxb <= 1; dxb++) {
                    int X = bx + dxb;
                    if (X < 0 || X >= NBX) continue;
                    int bb = (Z * NBX + Y) * NBX + X;
                    unsigned st = binStart[bb], cn = binCnt[bb];
                    for (unsigned p = 0; p < cn; p++) {
                        int a = binPts[st + p];
                        if (a < ci) {
                            float d2 = dist2(px, py, pz, cx[a], cy[a], cz[a]);
                            if (d2 < dd && nc < NNCAP)
                                nbr[ci * NNCAP + nc++] = (unsigned short)a;
                        }
                    }
                }
            }
        }
        nbrCnt[ci] = (unsigned char)nc;
    }
    __syncthreads();

    // ---- chunked greedy resolution, SPARSE sweep over nonzero rows ----
    // keep[j] <=> no earlier kept neighbor (exact sequential semantics).
    int nchunks = (m + 63) >> 6;
    for (int c = 0; c < nchunks; c++) {
        int cb = c * 64;
        int cc = min(64, m - cb);
        if (tid < 64) matS[tid] = 0ull;
        if (tid == 0) { supp = 0ull; nzmask = 0ull; }
        __syncthreads();

        int jj = tid >> 4, sub = tid & 15;   // 16 threads per chunk point
        if (jj < cc) {
            int j = cb + jj;
            if (sub < (int)nbrCnt[j]) {
                int a = nbr[j * NNCAP + sub];
                if (a < cb) {
                    if (state[a]) atomicOr(&supp, 1ull << jj);
                } else {
                    atomicOr(&matS[a - cb], 1ull << jj);
                    atomicOr(&nzmask, 1ull << (a - cb));
                }
            }
        }
        __syncthreads();

        if (tid == 0) {
            // rows are strictly upper-triangular (bits of matS[q] all > q) and
            // only nonzero rows mutate s => iterate set bits of nzmask in order;
            // final s gives keep for every point in the chunk.
            unsigned long long s = supp;
            unsigned long long rem = nzmask;
            while (rem) {
                int q = __ffsll((long long)rem) - 1;
                rem &= rem - 1;
                if (!((s >> q) & 1ull)) s |= matS[q];
            }
            unsigned long long km = ~s;
            for (int q = 0; q < cc; q++)
                state[cb + q] = (unsigned char)((km >> q) & 1ull);
        }
        __syncthreads();
    }

    // ---- keep mask scatter ----
    for (int ci = tid; ci < m; ci += NTH)
        fullk[spos[ci]] = state[ci];

    // ---- order-preserving compaction of kept -> g_k* ----
    {
        int base2 = tid * 2;
        int k0 = (base2 < m) ? (state[base2] == 1) : 0;
        int k1 = (base2 + 1 < m) ? (state[base2 + 1] == 1) : 0;
        int ex2 = blockScanExcl(k0 + k1, wsum, tid);   // barrier fences fullk scatter too
        int kc = wsum[31];
        int kb2 = prob * 2048;
        if (k0) {
            g_kx[kb2 + ex2] = cx[base2]; g_ky[kb2 + ex2] = cy[base2];
            g_kz[kb2 + ex2] = cz[base2]; g_kpos[kb2 + ex2] = spos[base2];
            ex2++;
        }
        if (k1) {
            g_kx[kb2 + ex2] = cx[base2 + 1]; g_ky[kb2 + ex2] = cy[base2 + 1];
            g_kz[kb2 + ex2] = cz[base2 + 1]; g_kpos[kb2 + ex2] = spos[base2 + 1];
        }
        if (tid == 0) g_kcnt[prob] = kc;
    }

    // ---- write keep mask ----
    int kb = (t ? OFF_KT : OFF_KP) + (b * 2 + e) * 4096;
    for (int q = 0; q < 4; q++) {
        int s = tid * 4 + q;
        out[kb + s] = (float)fullk[s];
    }
}

// ---------------------------------------------------------------------------
// Kernel D (8 blocks): matching with active-list wave resolution
// ---------------------------------------------------------------------------
__global__ void __launch_bounds__(1024) k_match(float* __restrict__ out)
{
    extern __shared__ unsigned char sm[];
    float* cpx = (float*)sm;
    float* cpy = (float*)(sm + 8 * 1024);
    float* cpz = (float*)(sm + 16 * 1024);
    float* ctx = (float*)(sm + 24 * 1024);
    float* cty = (float*)(sm + 32 * 1024);
    float* ctz = (float*)(sm + 40 * 1024);
    unsigned short* ppos = (unsigned short*)(sm + 48 * 1024);
    unsigned short* tpos = (unsigned short*)(sm + 52 * 1024);
    unsigned int* binCnt = (unsigned int*)(sm + 56 * 1024);
    unsigned int* binStart = (unsigned int*)(sm + 88 * 1024);
    unsigned short* binPts = (unsigned short*)(sm + 120 * 1024);
    unsigned char* candCnt = (unsigned char*)(sm + 124 * 1024);
    unsigned short* cand = (unsigned short*)(sm + 126 * 1024);
    unsigned char* tpF = (unsigned char*)(sm + 174 * 1024);
    unsigned char* mtF = (unsigned char*)(sm + 178 * 1024);
    unsigned int* taken = (unsigned int*)(sm + 182 * 1024);
    unsigned int* minIdx = (unsigned int*)(sm + 56 * 1024);    // alias binCnt
    unsigned short* actA = (unsigned short*)(sm + 88 * 1024);  // alias binStart
    unsigned short* actB = (unsigned short*)(sm + 92 * 1024);

    __shared__ int wsum[32];
    __shared__ int nact, nNext;

    const int tid = threadIdx.x;
    const int be = blockIdx.x;
    const int b = be >> 1, e = be & 1;
    const float de = (e == 0) ? (float)(0.74 * 1.4) : (float)(0.528 * 1.4);
    const float dd = __fmul_rn(de, de);
    const float cellXY = fmaxf(de, 1.02f);
    const float invXY = 1.0f / cellXY;
    const float invZ = 1.0f / 1.3125f;

    const int kpBase = OFF_KP + (b * 2 + e) * 4096;
    const int ktBase = OFF_KT + (b * 2 + e) * 4096;
    const int pP = be, pT = 8 + be;

    const int KP = min(g_kcnt[pP], 2048);
    const int KT = min(g_kcnt[pT], 2048);

    for (int i = tid; i < KP; i += NTH) {
        cpx[i] = g_kx[pP * 2048 + i];
        cpy[i] = g_ky[pP * 2048 + i];
        cpz[i] = g_kz[pP * 2048 + i];
        ppos[i] = g_kpos[pP * 2048 + i];
    }
    for (int i = tid; i < KT; i += NTH) {
        ctx[i] = g_kx[pT * 2048 + i];
        cty[i] = g_ky[pT * 2048 + i];
        ctz[i] = g_kz[pT * 2048 + i];
        tpos[i] = g_kpos[pT * 2048 + i];
    }
    for (int i = tid; i < NBX * NBX * NBZ; i += NTH) binCnt[i] = 0;
    if (tid < 64) taken[tid] = 0u;
    if (tid == 0) { nact = 0; nNext = 0; }
    for (int q = 0; q < 4; q++) { tpF[tid * 4 + q] = 0; mtF[tid * 4 + q] = 0; }
    __syncthreads();

    // ---- bin kept targets ----
    for (int ci = tid; ci < KT; ci += NTH) {
        int bx, by, bz;
        binCoords(ctx[ci], cty[ci], ctz[ci], invXY, invZ, bx, by, bz);
        atomicAdd(&binCnt[(bz * NBX + by) * NBX + bx], 1u);
    }
    __syncthreads();
    {
        int base8 = tid * 8;
        int loc[8]; int s = 0;
        for (int k2 = 0; k2 < 8; k2++) { loc[k2] = s; s += (int)binCnt[base8 + k2]; }
        int ex = blockScanExcl(s, wsum, tid);
        for (int k2 = 0; k2 < 8; k2++) binStart[base8 + k2] = (unsigned)(ex + loc[k2]);
    }
    __syncthreads();
    for (int i = tid; i < NBX * NBX * NBZ; i += NTH) binCnt[i] = 0;
    __syncthreads();
    for (int ci = tid; ci < KT; ci += NTH) {
        int bx, by, bz;
        binCoords(ctx[ci], cty[ci], ctz[ci], invXY, invZ, bx, by, bz);
        int bb = (bz * NBX + by) * NBX + bx;
        unsigned off = atomicAdd(&binCnt[bb], 1u);
        binPts[binStart[bb] + off] = (unsigned short)ci;
    }
    __syncthreads();

    // ---- per-pred sorted candidate lists ----
    for (int ci = tid; ci < KP; ci += NTH) {
        float px = cpx[ci], py = cpy[ci], pz = cpz[ci];
        int bx, by, bz;
        binCoords(px, py, pz, invXY, invZ, bx, by, bz);
        unsigned short* cl = cand + ci * CAP;
        int nc = 0;
        #pragma unroll
        for (int dzb = -1; dzb <= 1; dzb++) {
            int Z = bz + dzb;
            if (Z < 0 || Z >= NBZ) continue;
            #pragma unroll
            for (int dyb = -1; dyb <= 1; dyb++) {
                int Y = by + dyb;
                if (Y < 0 || Y >= NBX) continue;
                #pragma unroll
                for (int dxb = -1; dxb <= 1; dxb++) {
                    int X = bx + dxb;
                    if (X < 0 || X >= NBX) continue;
                    int bb = (Z * NBX + Y) * NBX + X;
                    unsigned st = binStart[bb], cn = binCnt[bb];
                    for (unsigned p = 0; p < cn; p++) {
                        int a = binPts[st + p];
                        float d2 = dist2(px, py, pz, ctx[a], cty[a], ctz[a]);
                        if (d2 < dd) {
                            if (nc < CAP) {
                                int k2 = nc;
                                while (k2 > 0 && cl[k2 - 1] > a) { cl[k2] = cl[k2 - 1]; k2--; }
                                cl[k2] = (unsigned short)a;
                                nc++;
                            } else if (a < cl[CAP - 1]) {
                                int k2 = CAP - 1;
                                while (k2 > 0 && cl[k2 - 1] > a) { cl[k2] = cl[k2 - 1]; k2--; }
                                cl[k2] = (unsigned short)a;
                            }
                        }
                    }
                }
            }
        }
        candCnt[ci] = (unsigned char)nc;
    }
    __syncthreads();     // bins dead; actA/actB alias binStart region

    // ---- initial active list ----
    for (int i = tid; i < KP; i += NTH) {
        if (candCnt[i] > 0) {
            int p = atomicAdd(&nact, 1);
            actA[p] = (unsigned short)i;
        }
    }
    int parity = 0;

    // ---- active-list wave resolution (exact sequential semantics) ----
    while (true) {
        __syncthreads();
        int na = nact;
        if (na <= 0) break;
        const unsigned short* A = parity ? actB : actA;
        unsigned short* Bn = parity ? actA : actB;

        for (int idx = tid; idx < na; idx += NTH) {
            int i = A[idx];
            int nc = candCnt[i];
            const unsigned short* cl = cand + i * CAP;
            for (int k2 = 0; k2 < nc; k2++) minIdx[cl[k2]] = 0x7FFFFFFFu;
        }
        if (tid == 0) nNext = 0;
        __syncthreads();
        for (int idx = tid; idx < na; idx += NTH) {
            int i = A[idx];
            int nc = candCnt[i];
            const unsigned short* cl = cand + i * CAP;
            for (int k2 = 0; k2 < nc; k2++)
                atomicMin(&minIdx[cl[k2]], (unsigned)i);
        }
        __syncthreads();
        for (int idx = tid; idx < na; idx += NTH) {
            int i = A[idx];
            int nc = candCnt[i];
            const unsigned short* cl = cand + i * CAP;
            bool ok = true;
            for (int k2 = 0; k2 < nc; k2++)
                if (minIdx[cl[k2]] < (unsigned)i) { ok = false; break; }
            if (ok) {
                for (int k2 = 0; k2 < nc; k2++) {
                    int j = cl[k2];
                    if (!((taken[j >> 5] >> (j & 31)) & 1u)) {
                        atomicOr(&taken[j >> 5], 1u << (j & 31));
                        tpF[ppos[i]] = 1;
                        mtF[tpos[j]] = 1;
                        break;
                    }
                }
            } else {
                int p = atomicAdd(&nNext, 1);
                Bn[p] = (unsigned short)i;
            }
        }
        __syncthreads();
        if (tid == 0) nact = nNext;
        parity ^= 1;
    }

    // ---- write tp/fp/fn ----
    const int tpB = OFF_TP + (b * 2 + e) * 4096;
    const int fpB = OFF_FP + (b * 2 + e) * 4096;
    const int fnB = OFF_FN + (b * 2 + e) * 4096;
    for (int q = 0; q < 4; q++) {
        int s = tid * 4 + q;
        int tp = tpF[s];
        int kp = (out[kpBase + s] > 0.5f) ? 1 : 0;
        int kt = (out[ktBase + s] > 0.5f) ? 1 : 0;
        out[tpB + s] = (float)tp;
        out[fpB + s] = (kp && !tp) ? 1.0f : 0.0f;
        out[fnB + s] = (kt && !mtF[s]) ? 1.0f : 0.0f;
    }
}

// ---------------------------------------------------------------------------
extern "C" void kernel_launch(void* const* d_in, const int* in_sizes, int n_in,
                              void* d_out, int out_size)
{
    const float* pred = (const float*)d_in[0];
    const float* targ = (const float*)d_in[1];
    float* out = (float*)d_out;

    cudaFuncSetAttribute(k_nms2, cudaFuncAttributeMaxDynamicSharedMemorySize, 168 * 1024);
    cudaFuncSetAttribute(k_match, cudaFuncAttributeMaxDynamicSharedMemorySize, 184 * 1024);

    k_sortA<<<64, NTH, 8 * 1024>>>(pred, targ);
    k_sortB<<<32, NTH, 16 * 1024>>>();
    k_coords<<<32, NTH, 32 * 1024>>>(pred, targ, out);
    k_nms2<<<16, NTH, 168 * 1024>>>(out);
    k_match<<<8, NTH, 184 * 1024>>>(out);
}

// round 11
// speedup vs baseline: 2.0170x; 2.0170x over previous
#include <cuda_runtime.h>
#include <cstdint>

#define NPTS 4096
#define NTH  1024

// d_out float32 layout:
//   Pc [4][2][4096][3] @0, Tc @98304, keepP @196608, keepT @229376,
//   tp @262144, fp @294912, fn @327680
#define OFF_TC 98304
#define OFF_KP 196608
#define OFF_KT 229376
#define OFF_TP 262144
#define OFF_FP 294912
#define OFF_FN 327680

#define NBX 32
#define NBZ 8
#define CAP 12
#define NNCAP 16
#define MAXV 2048

__device__ unsigned long long g_run0[16 * 4096];
__device__ unsigned long long g_run1[16 * 4096];
// per-half compacted valid points (sorted order preserved)
__device__ float g_vx[16 * 4096];
__device__ float g_vy[16 * 4096];
__device__ float g_vz[16 * 4096];
__device__ unsigned short g_vs[16 * 4096];   // sorted position 0..4095
__device__ int g_vcnt[32];
// NMS-kept compact lists per problem
__device__ float g_kx[16 * 2048];
__device__ float g_ky[16 * 2048];
__device__ float g_kz[16 * 2048];
__device__ unsigned short g_kpos[16 * 2048];
__device__ int g_kcnt[16];

__device__ __forceinline__ float dist2(float ax, float ay, float az,
                                       float bx, float by, float bz) {
    float dx = __fadd_rn(ax, -bx);
    float dy = __fadd_rn(ay, -by);
    float dz = __fadd_rn(az, -bz);
    return __fadd_rn(__fadd_rn(__fmul_rn(dx, dx), __fmul_rn(dy, dy)),
                     __fmul_rn(dz, dz));
}

__device__ __forceinline__ int clampi(int v, int lo, int hi) {
    return v < lo ? lo : (v > hi ? hi : v);
}

__device__ __forceinline__ void binCoords(float x, float y, float z,
                                          float invXY, float invZ,
                                          int& bx, int& by, int& bz) {
    bx = clampi((int)floorf(__fmul_rn(__fadd_rn(x, 4.5f), invXY)), 0, NBX - 1);
    by = clampi((int)floorf(__fmul_rn(__fadd_rn(y, 4.5f), invXY)), 0, NBX - 1);
    bz = clampi((int)floorf(__fmul_rn(__fadd_rn(z, 4.0f), invZ)),  0, NBZ - 1);
}

__device__ __forceinline__ int blockScanExcl(int cnt, int* wsum, int tid) {
    int lane = tid & 31, wid = tid >> 5;
    int v = cnt;
    for (int o = 1; o < 32; o <<= 1) {
        int nn = __shfl_up_sync(0xFFFFFFFFu, v, o);
        if (lane >= o) v += nn;
    }
    if (lane == 31) wsum[wid] = v;
    __syncthreads();
    if (wid == 0) {
        int w = wsum[lane];
        for (int o = 1; o < 32; o <<= 1) {
            int nn = __shfl_up_sync(0xFFFFFFFFu, w, o);
            if (lane >= o) w += nn;
        }
        wsum[lane] = w;
    }
    __syncthreads();
    return v - cnt + (wid ? wsum[wid - 1] : 0);
}

// ---------------------------------------------------------------------------
// Kernel A (64 blocks): sort 1024-key runs -> g_run0
// ---------------------------------------------------------------------------
__global__ void __launch_bounds__(1024) k_sortA(const float* __restrict__ pred,
                                                const float* __restrict__ targ)
{
    extern __shared__ unsigned char sm[];
    unsigned long long* s = (unsigned long long*)sm;   // [1024]
    const int tid = threadIdx.x;
    const int bi = blockIdx.x;
    const int prob = bi >> 2;
    const int quarter = bi & 3;
    const int t = prob >> 3;
    const int be = prob & 7;
    const int b = be >> 1;
    const int e = be & 1;
    const float* in = (t == 0) ? pred : targ;

    int n = quarter * 1024 + tid;
    int z = n >> 10, x = (n >> 5) & 31, y = n & 31;
    int base = ((((b * 32 + x) * 32 + y) * 4 + z) * 8) + e * 4;
    float conf = in[base + 3];
    unsigned u = __float_as_uint(conf);
    u = (u & 0x80000000u) ? ~u : (u | 0x80000000u);
    unsigned long long v = (((unsigned long long)(~u)) << 32) | (unsigned)n;

    for (int k = 2; k <= 1024; k <<= 1) {
        bool up = ((tid & k) == 0);
        for (int j = k >> 1; j > 0; j >>= 1) {
            unsigned long long p;
            if (j >= 32) {
                s[tid] = v;
                __syncthreads();
                p = s[tid ^ j];
                __syncthreads();
            } else {
                p = __shfl_xor_sync(0xFFFFFFFFu, v, j);
            }
            bool lower = ((tid & j) == 0);
            bool kmin = (lower == up);
            unsigned long long mn = v < p ? v : p;
            unsigned long long mx = v < p ? p : v;
            v = kmin ? mn : mx;
        }
    }
    g_run0[prob * 4096 + quarter * 1024 + tid] = v;
}

// ---------------------------------------------------------------------------
// Kernel B (32 blocks): merge 1024+1024 -> 2048 -> g_run1
// ---------------------------------------------------------------------------
__global__ void __launch_bounds__(1024) k_sortB()
{
    extern __shared__ unsigned char sm[];
    unsigned long long* sA = (unsigned long long*)sm;              // [1024]
    unsigned long long* sB = (unsigned long long*)(sm + 8 * 1024); // [1024]
    const int tid = threadIdx.x;
    const int prob = blockIdx.x >> 1;
    const int half = blockIdx.x & 1;
    const unsigned long long* src = g_run0 + prob * 4096 + half * 2048;
    sA[tid] = src[tid];
    sB[tid] = src[1024 + tid];
    __syncthreads();

    int diag = tid * 2;
    int lo = diag > 1024 ? diag - 1024 : 0;
    int hi = diag < 1024 ? diag : 1024;
    while (lo < hi) {
        int mid = (lo + hi) >> 1;
        if (sA[mid] < sB[diag - 1 - mid]) lo = mid + 1; else hi = mid;
    }
    int ai = lo, bj = diag - lo;
    unsigned long long* dst = g_run1 + prob * 4096 + half * 2048;
    #pragma unroll
    for (int r = 0; r < 2; r++) {
        bool takeA = (bj >= 1024) || (ai < 1024 && sA[ai] <= sB[bj]);
        dst[diag + r] = takeA ? sA[ai++] : sB[bj++];
    }
}

// ---------------------------------------------------------------------------
// Kernel C1 (32 blocks, 2/problem): merge-path half -> coords -> Pc/Tc
//   + per-half order-preserving valid compaction -> g_v*
// ---------------------------------------------------------------------------
__global__ void __launch_bounds__(1024) k_coords(const float* __restrict__ pred,
                                                 const float* __restrict__ targ,
                                                 float* __restrict__ out)
{
    extern __shared__ unsigned char sm[];
    unsigned long long* sA2 = (unsigned long long*)sm;             // [2048] 16KB
    unsigned long long* sB2 = (unsigned long long*)(sm + 16 * 1024);
    __shared__ int wsum[32];

    const int tid = threadIdx.x;
    const int bi = blockIdx.x;
    const int prob = bi >> 1;
    const int half = bi & 1;
    const int t = prob >> 3;
    const int be = prob & 7;
    const int b = be >> 1;
    const int e = be & 1;
    const float* in = (t == 0) ? pred : targ;

    {
        const unsigned long long* src = g_run1 + prob * 4096;
        sA2[tid] = src[tid];
        sA2[1024 + tid] = src[1024 + tid];
        sB2[tid] = src[2048 + tid];
        sB2[1024 + tid] = src[3072 + tid];
    }
    __syncthreads();

    const int diag = half * 2048 + tid * 2;
    int lo = diag > 2048 ? diag - 2048 : 0;
    int hi = diag < 2048 ? diag : 2048;
    while (lo < hi) {
        int mid = (lo + hi) >> 1;
        if (sA2[mid] < sB2[diag - 1 - mid]) lo = mid + 1; else hi = mid;
    }
    int ai = lo, bj = diag - lo;
    unsigned long long myk[2];
    #pragma unroll
    for (int r = 0; r < 2; r++) {
        bool takeA = (bj >= 2048) || (ai < 2048 && sA2[ai] <= sB2[bj]);
        myk[r] = takeA ? sA2[ai++] : sB2[bj++];
    }

    float rx[2], ry[2], rz[2];
    int vf[2]; int cnt = 0;
    #pragma unroll
    for (int q = 0; q < 2; q++) {
        int n = (int)(myk[q] & 0xFFFFFFFFull);
        int z = n >> 10, x = (n >> 5) & 31, y = n & 31;
        int base = ((((b * 32 + x) * 32 + y) * 4 + z) * 8) + e * 4;
        float4 vv = *(const float4*)(in + base);
        float c0 = __fmul_rn(__fadd_rn(vv.z, (float)z), 0.75f);
        float c1 = __fmul_rn(__fadd_rn(vv.x, (float)x), 0.78125f);
        float c2 = __fmul_rn(__fadd_rn(vv.y, (float)y), 0.78125f);
        rx[q] = c0; ry[q] = c1; rz[q] = c2;
        vf[q] = (vv.w > 0.5f) ? 1 : 0;
        cnt += vf[q];
        int s = diag + q;
        int ob = (t ? OFF_TC : 0) + ((b * 2 + e) * 4096 + s) * 3;
        out[ob + 0] = c0; out[ob + 1] = c1; out[ob + 2] = c2;
    }

    int excl = blockScanExcl(cnt, wsum, tid);
    int gb = prob * 4096 + half * 2048;
    #pragma unroll
    for (int q = 0; q < 2; q++) {
        if (vf[q]) {
            g_vx[gb + excl] = rx[q];
            g_vy[gb + excl] = ry[q];
            g_vz[gb + excl] = rz[q];
            g_vs[gb + excl] = (unsigned short)(diag + q);
            excl++;
        }
    }
    if (tid == 0) g_vcnt[bi] = wsum[31];
}

// ---------------------------------------------------------------------------
// Kernel C2 (16 blocks): stitch halves -> bins -> neighbor lists -> wave NMS
//   -> keep masks in out; kept compact lists -> g_k*
// ---------------------------------------------------------------------------
__global__ void __launch_bounds__(1024) k_nms2(float* __restrict__ out)
{
    extern __shared__ unsigned char sm[];
    float* cx = (float*)sm;                                      // 8KB
    float* cy = (float*)(sm + 8 * 1024);
    float* cz = (float*)(sm + 16 * 1024);
    unsigned short* spos = (unsigned short*)(sm + 24 * 1024);    // 4KB
    unsigned char* fullk = (unsigned char*)(sm + 28 * 1024);     // 4KB
    unsigned short* nbr = (unsigned short*)(sm + 32 * 1024);     // 64KB
    unsigned int* binCnt = (unsigned int*)(sm + 96 * 1024);      // 32KB
    unsigned int* binStart = (unsigned int*)(sm + 128 * 1024);   // 32KB
    unsigned short* binPts = (unsigned short*)(sm + 160 * 1024); // 4KB
    unsigned char* nbrCnt = (unsigned char*)(sm + 164 * 1024);   // 2KB
    unsigned char* state = (unsigned char*)(sm + 166 * 1024);    // 2KB

    __shared__ int wsum[32];
    __shared__ int remaining;

    const int tid = threadIdx.x;
    const int prob = blockIdx.x;
    const int t = prob >> 3;
    const int be = prob & 7;
    const int b = be >> 1;
    const int e = be & 1;
    const float de = (e == 0) ? (float)(0.74 * 1.4) : (float)(0.528 * 1.4);
    const float dd = __fmul_rn(de, de);
    const float cellXY = fmaxf(de, 1.02f);
    const float invXY = 1.0f / cellXY;
    const float invZ = 1.0f / 1.3125f;

    const int c0 = min(g_vcnt[prob * 2], MAXV);
    const int c1 = g_vcnt[prob * 2 + 1];
    const int m = min(c0 + c1, MAXV);
    const int gb = prob * 4096;

    // stitch halves (order-preserving: half0 then half1)
    for (int i = tid; i < c0; i += NTH) {
        cx[i] = g_vx[gb + i]; cy[i] = g_vy[gb + i]; cz[i] = g_vz[gb + i];
        spos[i] = g_vs[gb + i];
    }
    for (int i = tid; i < m - c0; i += NTH) {
        cx[c0 + i] = g_vx[gb + 2048 + i];
        cy[c0 + i] = g_vy[gb + 2048 + i];
        cz[c0 + i] = g_vz[gb + 2048 + i];
        spos[c0 + i] = g_vs[gb + 2048 + i];
    }
    for (int i = tid; i < NBX * NBX * NBZ; i += NTH) binCnt[i] = 0;
    for (int q = 0; q < 4; q++) fullk[tid * 4 + q] = 0;
    if (tid == 0) remaining = 0;
    __syncthreads();

    // ---- bins ----
    for (int ci = tid; ci < m; ci += NTH) {
        int bx, by, bz;
        binCoords(cx[ci], cy[ci], cz[ci], invXY, invZ, bx, by, bz);
        atomicAdd(&binCnt[(bz * NBX + by) * NBX + bx], 1u);
    }
    __syncthreads();
    {
        int base8 = tid * 8;
        int loc[8]; int s = 0;
        for (int k2 = 0; k2 < 8; k2++) { loc[k2] = s; s += (int)binCnt[base8 + k2]; }
        int ex = blockScanExcl(s, wsum, tid);
        for (int k2 = 0; k2 < 8; k2++) binStart[base8 + k2] = (unsigned)(ex + loc[k2]);
    }
    __syncthreads();
    for (int i = tid; i < NBX * NBX * NBZ; i += NTH) binCnt[i] = 0;
    __syncthreads();
    for (int ci = tid; ci < m; ci += NTH) {
        int bx, by, bz;
        binCoords(cx[ci], cy[ci], cz[ci], invXY, invZ, bx, by, bz);
        int bb = (bz * NBX + by) * NBX + bx;
        unsigned off = atomicAdd(&binCnt[bb], 1u);
        binPts[binStart[bb] + off] = (unsigned short)ci;
    }
    __syncthreads();

    // ---- one-pass earlier-neighbor lists ----
    {
        int undec = 0;
        for (int ci = tid; ci < m; ci += NTH) {
            float px = cx[ci], py = cy[ci], pz = cz[ci];
            int bx, by, bz;
            binCoords(px, py, pz, invXY, invZ, bx, by, bz);
            int nc = 0;
            #pragma unroll
            for (int dzb = -1; dzb <= 1; dzb++) {
                int Z = bz + dzb;
                if (Z < 0 || Z >= NBZ) continue;
                #pragma unroll
                for (int dyb = -1; dyb <= 1; dyb++) {
                    int Y = by + dyb;
                    if (Y < 0 || Y >= NBX) continue;
                    #pragma unroll
                    for (int dxb = -1; dxb <= 1; dxb++) {
                        int X = bx + dxb;
                        if (X < 0 || X >= NBX) continue;
                        int bb = (Z * NBX + Y) * NBX + X;
                        unsigned st = binStart[bb], cn = binCnt[bb];
                        for (unsigned p = 0; p < cn; p++) {
                            int a = binPts[st + p];
                            if (a < ci) {
                                float d2 = dist2(px, py, pz, cx[a], cy[a], cz[a]);
                                if (d2 < dd && nc < NNCAP)
                                    nbr[ci * NNCAP + nc++] = (unsigned short)a;
                            }
                        }
                    }
                }
            }
            nbrCnt[ci] = (unsigned char)nc;
            int st0 = (nc == 0) ? 1 : 0;
            state[ci] = (unsigned char)st0;
            undec += (st0 == 0);
        }
        if (undec) atomicAdd(&remaining, undec);
    }
    __syncthreads();

    // ---- wave NMS resolution (exact sequential semantics) ----
    while (true) {
        if (remaining <= 0) break;
        int dec = 0;
        for (int ci = tid; ci < m; ci += NTH) {
            if (state[ci] == 0) {
                int nc = nbrCnt[ci];
                bool anyK = false, allS = true;
                for (int k2 = 0; k2 < nc; k2++) {
                    unsigned char s2 = state[nbr[ci * NNCAP + k2]];
                    anyK |= (s2 == 1);
                    allS &= (s2 == 2);
                }
                if (anyK) { state[ci] = 2; dec++; }
                else if (allS) { state[ci] = 1; dec++; }
            }
        }
        if (dec) atomicSub(&remaining, dec);
        __syncthreads();
    }

    // ---- keep mask scatter ----
    for (int ci = tid; ci < m; ci += NTH)
        fullk[spos[ci]] = (state[ci] == 1) ? 1 : 0;

    // ---- order-preserving compaction of kept -> g_k* ----
    {
        int base2 = tid * 2;
        int k0 = (base2 < m) ? (state[base2] == 1) : 0;
        int k1 = (base2 + 1 < m) ? (state[base2 + 1] == 1) : 0;
        int ex2 = blockScanExcl(k0 + k1, wsum, tid);   // barrier fences fullk scatter too
        int kc = wsum[31];
        int kb2 = prob * 2048;
        if (k0) {
            g_kx[kb2 + ex2] = cx[base2]; g_ky[kb2 + ex2] = cy[base2];
            g_kz[kb2 + ex2] = cz[base2]; g_kpos[kb2 + ex2] = spos[base2];
            ex2++;
        }
        if (k1) {
            g_kx[kb2 + ex2] = cx[base2 + 1]; g_ky[kb2 + ex2] = cy[base2 + 1];
            g_kz[kb2 + ex2] = cz[base2 + 1]; g_kpos[kb2 + ex2] = spos[base2 + 1];
        }
        if (tid == 0) g_kcnt[prob] = kc;
    }

    // ---- write keep mask ----
    int kb = (t ? OFF_KT : OFF_KP) + (b * 2 + e) * 4096;
    for (int q = 0; q < 4; q++) {
        int s = tid * 4 + q;
        out[kb + s] = (float)fullk[s];
    }
}

// ---------------------------------------------------------------------------
// Kernel D (8 blocks): matching with active-list wave resolution
// ---------------------------------------------------------------------------
__global__ void __launch_bounds__(1024) k_match(float* __restrict__ out)
{
    extern __shared__ unsigned char sm[];
    float* cpx = (float*)sm;
    float* cpy = (float*)(sm + 8 * 1024);
    float* cpz = (float*)(sm + 16 * 1024);
    float* ctx = (float*)(sm + 24 * 1024);
    float* cty = (float*)(sm + 32 * 1024);
    float* ctz = (float*)(sm + 40 * 1024);
    unsigned short* ppos = (unsigned short*)(sm + 48 * 1024);
    unsigned short* tpos = (unsigned short*)(sm + 52 * 1024);
    unsigned int* binCnt = (unsigned int*)(sm + 56 * 1024);
    unsigned int* binStart = (unsigned int*)(sm + 88 * 1024);
    unsigned short* binPts = (unsigned short*)(sm + 120 * 1024);
    unsigned char* candCnt = (unsigned char*)(sm + 124 * 1024);
    unsigned short* cand = (unsigned short*)(sm + 126 * 1024);
    unsigned char* tpF = (unsigned char*)(sm + 174 * 1024);
    unsigned char* mtF = (unsigned char*)(sm + 178 * 1024);
    unsigned int* taken = (unsigned int*)(sm + 182 * 1024);
    unsigned int* minIdx = (unsigned int*)(sm + 56 * 1024);    // alias binCnt
    unsigned short* actA = (unsigned short*)(sm + 88 * 1024);  // alias binStart
    unsigned short* actB = (unsigned short*)(sm + 92 * 1024);

    __shared__ int wsum[32];
    __shared__ int nact, nNext;

    const int tid = threadIdx.x;
    const int be = blockIdx.x;
    const int b = be >> 1, e = be & 1;
    const float de = (e == 0) ? (float)(0.74 * 1.4) : (float)(0.528 * 1.4);
    const float dd = __fmul_rn(de, de);
    const float cellXY = fmaxf(de, 1.02f);
    const float invXY = 1.0f / cellXY;
    const float invZ = 1.0f / 1.3125f;

    const int kpBase = OFF_KP + (b * 2 + e) * 4096;
    const int ktBase = OFF_KT + (b * 2 + e) * 4096;
    const int pP = be, pT = 8 + be;

    const int KP = min(g_kcnt[pP], 2048);
    const int KT = min(g_kcnt[pT], 2048);

    for (int i = tid; i < KP; i += NTH) {
        cpx[i] = g_kx[pP * 2048 + i];
        cpy[i] = g_ky[pP * 2048 + i];
        cpz[i] = g_kz[pP * 2048 + i];
        ppos[i] = g_kpos[pP * 2048 + i];
    }
    for (int i = tid; i < KT; i += NTH) {
        ctx[i] = g_kx[pT * 2048 + i];
        cty[i] = g_ky[pT * 2048 + i];
        ctz[i] = g_kz[pT * 2048 + i];
        tpos[i] = g_kpos[pT * 2048 + i];
    }
    for (int i = tid; i < NBX * NBX * NBZ; i += NTH) binCnt[i] = 0;
    if (tid < 64) taken[tid] = 0u;
    if (tid == 0) { nact = 0; nNext = 0; }
    for (int q = 0; q < 4; q++) { tpF[tid * 4 + q] = 0; mtF[tid * 4 + q] = 0; }
    __syncthreads();

    // ---- bin kept targets ----
    for (int ci = tid; ci < KT; ci += NTH) {
        int bx, by, bz;
        binCoords(ctx[ci], cty[ci], ctz[ci], invXY, invZ, bx, by, bz);
        atomicAdd(&binCnt[(bz * NBX + by) * NBX + bx], 1u);
    }
    __syncthreads();
    {
        int base8 = tid * 8;
        int loc[8]; int s = 0;
        for (int k2 = 0; k2 < 8; k2++) { loc[k2] = s; s += (int)binCnt[base8 + k2]; }
        int ex = blockScanExcl(s, wsum, tid);
        for (int k2 = 0; k2 < 8; k2++) binStart[base8 + k2] = (unsigned)(ex + loc[k2]);
    }
    __syncthreads();
    for (int i = tid; i < NBX * NBX * NBZ; i += NTH) binCnt[i] = 0;
    __syncthreads();
    for (int ci = tid; ci < KT; ci += NTH) {
        int bx, by, bz;
        binCoords(ctx[ci], cty[ci], ctz[ci], invXY, invZ, bx, by, bz);
        int bb = (bz * NBX + by) * NBX + bx;
        unsigned off = atomicAdd(&binCnt[bb], 1u);
        binPts[binStart[bb] + off] = (unsigned short)ci;
    }
    __syncthreads();

    // ---- per-pred sorted candidate lists ----
    for (int ci = tid; ci < KP; ci += NTH) {
        float px = cpx[ci], py = cpy[ci], pz = cpz[ci];
        int bx, by, bz;
        binCoords(px, py, pz, invXY, invZ, bx, by, bz);
        unsigned short* cl = cand + ci * CAP;
        int nc = 0;
        #pragma unroll
        for (int dzb = -1; dzb <= 1; dzb++) {
            int Z = bz + dzb;
            if (Z < 0 || Z >= NBZ) continue;
            #pragma unroll
            for (int dyb = -1; dyb <= 1; dyb++) {
                int Y = by + dyb;
                if (Y < 0 || Y >= NBX) continue;
                #pragma unroll
                for (int dxb = -1; dxb <= 1; dxb++) {
                    int X = bx + dxb;
                    if (X < 0 || X >= NBX) continue;
                    int bb = (Z * NBX + Y) * NBX + X;
                    unsigned st = binStart[bb], cn = binCnt[bb];
                    for (unsigned p = 0; p < cn; p++) {
                        int a = binPts[st + p];
                        float d2 = dist2(px, py, pz, ctx[a], cty[a], ctz[a]);
                        if (d2 < dd) {
                            if (nc < CAP) {
                                int k2 = nc;
                                while (k2 > 0 && cl[k2 - 1] > a) { cl[k2] = cl[k2 - 1]; k2--; }
                                cl[k2] = (unsigned short)a;
                                nc++;
                            } else if (a < cl[CAP - 1]) {
                                int k2 = CAP - 1;
                                while (k2 > 0 && cl[k2 - 1] > a) { cl[k2] = cl[k2 - 1]; k2--; }
                                cl[k2] = (unsigned short)a;
                            }
                        }
                    }
                }
            }
        }
        candCnt[ci] = (unsigned char)nc;
    }
    __syncthreads();     // bins dead; actA/actB alias binStart region

    // ---- initial active list ----
    for (int i = tid; i < KP; i += NTH) {
        if (candCnt[i] > 0) {
            int p = atomicAdd(&nact, 1);
            actA[p] = (unsigned short)i;
        }
    }
    int parity = 0;

    // ---- active-list wave resolution (exact sequential semantics) ----
    while (true) {
        __syncthreads();
        int na = nact;
        if (na <= 0) break;
        const unsigned short* A = parity ? actB : actA;
        unsigned short* Bn = parity ? actA : actB;

        for (int idx = tid; idx < na; idx += NTH) {
            int i = A[idx];
            int nc = candCnt[i];
            const unsigned short* cl = cand + i * CAP;
            for (int k2 = 0; k2 < nc; k2++) minIdx[cl[k2]] = 0x7FFFFFFFu;
        }
        if (tid == 0) nNext = 0;
        __syncthreads();
        for (int idx = tid; idx < na; idx += NTH) {
            int i = A[idx];
            int nc = candCnt[i];
            const unsigned short* cl = cand + i * CAP;
            for (int k2 = 0; k2 < nc; k2++)
                atomicMin(&minIdx[cl[k2]], (unsigned)i);
        }
        __syncthreads();
        for (int idx = tid; idx < na; idx += NTH) {
            int i = A[idx];
            int nc = candCnt[i];
            const unsigned short* cl = cand + i * CAP;
            bool ok = true;
            for (int k2 = 0; k2 < nc; k2++)
                if (minIdx[cl[k2]] < (unsigned)i) { ok = false; break; }
            if (ok) {
                for (int k2 = 0; k2 < nc; k2++) {
                    int j = cl[k2];
                    if (!((taken[j >> 5] >> (j & 31)) & 1u)) {
                        atomicOr(&taken[j >> 5], 1u << (j & 31));
                        tpF[ppos[i]] = 1;
                        mtF[tpos[j]] = 1;
                        break;
                    }
                }
            } else {
                int p = atomicAdd(&nNext, 1);
                Bn[p] = (unsigned short)i;
            }
        }
        __syncthreads();
        if (tid == 0) nact = nNext;
        parity ^= 1;
    }

    // ---- write tp/fp/fn ----
    const int tpB = OFF_TP + (b * 2 + e) * 4096;
    const int fpB = OFF_FP + (b * 2 + e) * 4096;
    const int fnB = OFF_FN + (b * 2 + e) * 4096;
    for (int q = 0; q < 4; q++) {
        int s = tid * 4 + q;
        int tp = tpF[s];
        int kp = (out[kpBase + s] > 0.5f) ? 1 : 0;
        int kt = (out[ktBase + s] > 0.5f) ? 1 : 0;
        out[tpB + s] = (float)tp;
        out[fpB + s] = (kp && !tp) ? 1.0f : 0.0f;
        out[fnB + s] = (kt && !mtF[s]) ? 1.0f : 0.0f;
    }
}

// ---------------------------------------------------------------------------
extern "C" void kernel_launch(void* const* d_in, const int* in_sizes, int n_in,
                              void* d_out, int out_size)
{
    const float* pred = (const float*)d_in[0];
    const float* targ = (const float*)d_in[1];
    float* out = (float*)d_out;

    cudaFuncSetAttribute(k_nms2, cudaFuncAttributeMaxDynamicSharedMemorySize, 168 * 1024);
    cudaFuncSetAttribute(k_match, cudaFuncAttributeMaxDynamicSharedMemorySize, 184 * 1024);

    k_sortA<<<64, NTH, 8 * 1024>>>(pred, targ);
    k_sortB<<<32, NTH, 16 * 1024>>>();
    k_coords<<<32, NTH, 32 * 1024>>>(pred, targ, out);
    k_nms2<<<16, NTH, 168 * 1024>>>(out);
    k_match<<<8, NTH, 184 * 1024>>>(out);
}

// round 12
// speedup vs baseline: 2.3944x; 1.1871x over previous
#include <cuda_runtime.h>
#include <cstdint>

#define NPTS 4096
#define NTH  1024

// d_out float32 layout:
//   Pc [4][2][4096][3] @0, Tc @98304, keepP @196608, keepT @229376,
//   tp @262144, fp @294912, fn @327680
#define OFF_TC 98304
#define OFF_KP 196608
#define OFF_KT 229376
#define OFF_TP 262144
#define OFF_FP 294912
#define OFF_FN 327680

#define NBX 32
#define NBZ 8
#define CAP 12
#define NNCAP 16
#define MAXV 2048

__device__ unsigned long long g_run0[16 * 4096];
__device__ unsigned long long g_run1[16 * 4096];
// per-half compacted valid points (sorted order preserved)
__device__ float g_vx[16 * 4096];
__device__ float g_vy[16 * 4096];
__device__ float g_vz[16 * 4096];
__device__ unsigned short g_vs[16 * 4096];   // sorted position 0..4095
__device__ int g_vcnt[32];
// NMS-kept compact lists per problem
__device__ float g_kx[16 * 2048];
__device__ float g_ky[16 * 2048];
__device__ float g_kz[16 * 2048];
__device__ unsigned short g_kpos[16 * 2048];
__device__ int g_kcnt[16];

__device__ __forceinline__ float dist2(float ax, float ay, float az,
                                       float bx, float by, float bz) {
    float dx = __fadd_rn(ax, -bx);
    float dy = __fadd_rn(ay, -by);
    float dz = __fadd_rn(az, -bz);
    return __fadd_rn(__fadd_rn(__fmul_rn(dx, dx), __fmul_rn(dy, dy)),
                     __fmul_rn(dz, dz));
}

__device__ __forceinline__ int clampi(int v, int lo, int hi) {
    return v < lo ? lo : (v > hi ? hi : v);
}

__device__ __forceinline__ void binCoords(float x, float y, float z,
                                          float invXY, float invZ,
                                          int& bx, int& by, int& bz) {
    bx = clampi((int)floorf(__fmul_rn(__fadd_rn(x, 4.5f), invXY)), 0, NBX - 1);
    by = clampi((int)floorf(__fmul_rn(__fadd_rn(y, 4.5f), invXY)), 0, NBX - 1);
    bz = clampi((int)floorf(__fmul_rn(__fadd_rn(z, 4.0f), invZ)),  0, NBZ - 1);
}

__device__ __forceinline__ int blockScanExcl(int cnt, int* wsum, int tid) {
    int lane = tid & 31, wid = tid >> 5;
    int v = cnt;
    for (int o = 1; o < 32; o <<= 1) {
        int nn = __shfl_up_sync(0xFFFFFFFFu, v, o);
        if (lane >= o) v += nn;
    }
    if (lane == 31) wsum[wid] = v;
    __syncthreads();
    if (wid == 0) {
        int w = wsum[lane];
        for (int o = 1; o < 32; o <<= 1) {
            int nn = __shfl_up_sync(0xFFFFFFFFu, w, o);
            if (lane >= o) w += nn;
        }
        wsum[lane] = w;
    }
    __syncthreads();
    return v - cnt + (wid ? wsum[wid - 1] : 0);
}

// ---------------------------------------------------------------------------
// Kernel A (64 blocks): sort 1024-key runs -> g_run0
// ---------------------------------------------------------------------------
__global__ void __launch_bounds__(1024) k_sortA(const float* __restrict__ pred,
                                                const float* __restrict__ targ)
{
    extern __shared__ unsigned char sm[];
    unsigned long long* s = (unsigned long long*)sm;   // [1024]
    const int tid = threadIdx.x;
    const int bi = blockIdx.x;
    const int prob = bi >> 2;
    const int quarter = bi & 3;
    const int t = prob >> 3;
    const int be = prob & 7;
    const int b = be >> 1;
    const int e = be & 1;
    const float* in = (t == 0) ? pred : targ;

    int n = quarter * 1024 + tid;
    int z = n >> 10, x = (n >> 5) & 31, y = n & 31;
    int base = ((((b * 32 + x) * 32 + y) * 4 + z) * 8) + e * 4;
    float conf = in[base + 3];
    unsigned u = __float_as_uint(conf);
    u = (u & 0x80000000u) ? ~u : (u | 0x80000000u);
    unsigned long long v = (((unsigned long long)(~u)) << 32) | (unsigned)n;

    for (int k = 2; k <= 1024; k <<= 1) {
        bool up = ((tid & k) == 0);
        for (int j = k >> 1; j > 0; j >>= 1) {
            unsigned long long p;
            if (j >= 32) {
                s[tid] = v;
                __syncthreads();
                p = s[tid ^ j];
                __syncthreads();
            } else {
                p = __shfl_xor_sync(0xFFFFFFFFu, v, j);
            }
            bool lower = ((tid & j) == 0);
            bool kmin = (lower == up);
            unsigned long long mn = v < p ? v : p;
            unsigned long long mx = v < p ? p : v;
            v = kmin ? mn : mx;
        }
    }
    g_run0[prob * 4096 + quarter * 1024 + tid] = v;
}

// ---------------------------------------------------------------------------
// Kernel B (32 blocks): merge 1024+1024 -> 2048 -> g_run1
// ---------------------------------------------------------------------------
__global__ void __launch_bounds__(1024) k_sortB()
{
    extern __shared__ unsigned char sm[];
    unsigned long long* sA = (unsigned long long*)sm;              // [1024]
    unsigned long long* sB = (unsigned long long*)(sm + 8 * 1024); // [1024]
    const int tid = threadIdx.x;
    const int prob = blockIdx.x >> 1;
    const int half = blockIdx.x & 1;
    const unsigned long long* src = g_run0 + prob * 4096 + half * 2048;
    sA[tid] = src[tid];
    sB[tid] = src[1024 + tid];
    __syncthreads();

    int diag = tid * 2;
    int lo = diag > 1024 ? diag - 1024 : 0;
    int hi = diag < 1024 ? diag : 1024;
    while (lo < hi) {
        int mid = (lo + hi) >> 1;
        if (sA[mid] < sB[diag - 1 - mid]) lo = mid + 1; else hi = mid;
    }
    int ai = lo, bj = diag - lo;
    unsigned long long* dst = g_run1 + prob * 4096 + half * 2048;
    #pragma unroll
    for (int r = 0; r < 2; r++) {
        bool takeA = (bj >= 1024) || (ai < 1024 && sA[ai] <= sB[bj]);
        dst[diag + r] = takeA ? sA[ai++] : sB[bj++];
    }
}

// ---------------------------------------------------------------------------
// Kernel C1 (32 blocks, 2/problem): merge-path half -> coords -> Pc/Tc
//   + per-half order-preserving valid compaction -> g_v*
// ---------------------------------------------------------------------------
__global__ void __launch_bounds__(1024) k_coords(const float* __restrict__ pred,
                                                 const float* __restrict__ targ,
                                                 float* __restrict__ out)
{
    extern __shared__ unsigned char sm[];
    unsigned long long* sA2 = (unsigned long long*)sm;             // [2048] 16KB
    unsigned long long* sB2 = (unsigned long long*)(sm + 16 * 1024);
    __shared__ int wsum[32];

    const int tid = threadIdx.x;
    const int bi = blockIdx.x;
    const int prob = bi >> 1;
    const int half = bi & 1;
    const int t = prob >> 3;
    const int be = prob & 7;
    const int b = be >> 1;
    const int e = be & 1;
    const float* in = (t == 0) ? pred : targ;

    {
        const unsigned long long* src = g_run1 + prob * 4096;
        sA2[tid] = src[tid];
        sA2[1024 + tid] = src[1024 + tid];
        sB2[tid] = src[2048 + tid];
        sB2[1024 + tid] = src[3072 + tid];
    }
    __syncthreads();

    const int diag = half * 2048 + tid * 2;
    int lo = diag > 2048 ? diag - 2048 : 0;
    int hi = diag < 2048 ? diag : 2048;
    while (lo < hi) {
        int mid = (lo + hi) >> 1;
        if (sA2[mid] < sB2[diag - 1 - mid]) lo = mid + 1; else hi = mid;
    }
    int ai = lo, bj = diag - lo;
    unsigned long long myk[2];
    #pragma unroll
    for (int r = 0; r < 2; r++) {
        bool takeA = (bj >= 2048) || (ai < 2048 && sA2[ai] <= sB2[bj]);
        myk[r] = takeA ? sA2[ai++] : sB2[bj++];
    }

    float rx[2], ry[2], rz[2];
    int vf[2]; int cnt = 0;
    #pragma unroll
    for (int q = 0; q < 2; q++) {
        int n = (int)(myk[q] & 0xFFFFFFFFull);
        int z = n >> 10, x = (n >> 5) & 31, y = n & 31;
        int base = ((((b * 32 + x) * 32 + y) * 4 + z) * 8) + e * 4;
        float4 vv = *(const float4*)(in + base);
        float c0 = __fmul_rn(__fadd_rn(vv.z, (float)z), 0.75f);
        float c1 = __fmul_rn(__fadd_rn(vv.x, (float)x), 0.78125f);
        float c2 = __fmul_rn(__fadd_rn(vv.y, (float)y), 0.78125f);
        rx[q] = c0; ry[q] = c1; rz[q] = c2;
        vf[q] = (vv.w > 0.5f) ? 1 : 0;
        cnt += vf[q];
        int s = diag + q;
        int ob = (t ? OFF_TC : 0) + ((b * 2 + e) * 4096 + s) * 3;
        out[ob + 0] = c0; out[ob + 1] = c1; out[ob + 2] = c2;
    }

    int excl = blockScanExcl(cnt, wsum, tid);
    int gb = prob * 4096 + half * 2048;
    #pragma unroll
    for (int q = 0; q < 2; q++) {
        if (vf[q]) {
            g_vx[gb + excl] = rx[q];
            g_vy[gb + excl] = ry[q];
            g_vz[gb + excl] = rz[q];
            g_vs[gb + excl] = (unsigned short)(diag + q);
            excl++;
        }
    }
    if (tid == 0) g_vcnt[bi] = wsum[31];
}

// ---------------------------------------------------------------------------
// Kernel C2 (16 blocks): stitch halves -> bins -> neighbor lists (x-range
// scan) -> wave NMS -> keep masks in out; kept compact lists -> g_k*
// ---------------------------------------------------------------------------
__global__ void __launch_bounds__(1024) k_nms2(float* __restrict__ out)
{
    extern __shared__ unsigned char sm[];
    float* cx = (float*)sm;                                      // 8KB
    float* cy = (float*)(sm + 8 * 1024);
    float* cz = (float*)(sm + 16 * 1024);
    unsigned short* spos = (unsigned short*)(sm + 24 * 1024);    // 4KB
    unsigned char* fullk = (unsigned char*)(sm + 28 * 1024);     // 4KB
    unsigned short* nbr = (unsigned short*)(sm + 32 * 1024);     // 64KB
    unsigned int* binCnt = (unsigned int*)(sm + 96 * 1024);      // 32KB
    unsigned int* binStart = (unsigned int*)(sm + 128 * 1024);   // 32KB
    unsigned short* binPts = (unsigned short*)(sm + 160 * 1024); // 4KB
    unsigned char* nbrCnt = (unsigned char*)(sm + 164 * 1024);   // 2KB
    unsigned char* state = (unsigned char*)(sm + 166 * 1024);    // 2KB

    __shared__ int wsum[32];
    __shared__ int remaining;

    const int tid = threadIdx.x;
    const int prob = blockIdx.x;
    const int t = prob >> 3;
    const int be = prob & 7;
    const int b = be >> 1;
    const int e = be & 1;
    const float de = (e == 0) ? (float)(0.74 * 1.4) : (float)(0.528 * 1.4);
    const float dd = __fmul_rn(de, de);
    const float cellXY = fmaxf(de, 1.02f);
    const float invXY = 1.0f / cellXY;
    const float invZ = 1.0f / 1.3125f;

    const int c0 = min(g_vcnt[prob * 2], MAXV);
    const int c1 = g_vcnt[prob * 2 + 1];
    const int m = min(c0 + c1, MAXV);
    const int gb = prob * 4096;

    // stitch halves (order-preserving: half0 then half1)
    for (int i = tid; i < c0; i += NTH) {
        cx[i] = g_vx[gb + i]; cy[i] = g_vy[gb + i]; cz[i] = g_vz[gb + i];
        spos[i] = g_vs[gb + i];
    }
    for (int i = tid; i < m - c0; i += NTH) {
        cx[c0 + i] = g_vx[gb + 2048 + i];
        cy[c0 + i] = g_vy[gb + 2048 + i];
        cz[c0 + i] = g_vz[gb + 2048 + i];
        spos[c0 + i] = g_vs[gb + 2048 + i];
    }
    for (int i = tid; i < NBX * NBX * NBZ; i += NTH) binCnt[i] = 0;
    for (int q = 0; q < 4; q++) fullk[tid * 4 + q] = 0;
    if (tid == 0) remaining = 0;
    __syncthreads();

    // ---- bins ----
    for (int ci = tid; ci < m; ci += NTH) {
        int bx, by, bz;
        binCoords(cx[ci], cy[ci], cz[ci], invXY, invZ, bx, by, bz);
        atomicAdd(&binCnt[(bz * NBX + by) * NBX + bx], 1u);
    }
    __syncthreads();
    {
        int base8 = tid * 8;
        int loc[8]; int s = 0;
        for (int k2 = 0; k2 < 8; k2++) { loc[k2] = s; s += (int)binCnt[base8 + k2]; }
        int ex = blockScanExcl(s, wsum, tid);
        for (int k2 = 0; k2 < 8; k2++) binStart[base8 + k2] = (unsigned)(ex + loc[k2]);
    }
    __syncthreads();
    for (int i = tid; i < NBX * NBX * NBZ; i += NTH) binCnt[i] = 0;
    __syncthreads();
    for (int ci = tid; ci < m; ci += NTH) {
        int bx, by, bz;
        binCoords(cx[ci], cy[ci], cz[ci], invXY, invZ, bx, by, bz);
        int bb = (bz * NBX + by) * NBX + bx;
        unsigned off = atomicAdd(&binCnt[bb], 1u);
        binPts[binStart[bb] + off] = (unsigned short)ci;
    }
    __syncthreads();

    // ---- one-pass earlier-neighbor lists (contiguous x-range scan) ----
    {
        int undec = 0;
        for (int ci = tid; ci < m; ci += NTH) {
            float px = cx[ci], py = cy[ci], pz = cz[ci];
            int bx, by, bz;
            binCoords(px, py, pz, invXY, invZ, bx, by, bz);
            int x0 = bx > 0 ? bx - 1 : 0;
            int x1 = bx < NBX - 1 ? bx + 1 : NBX - 1;
            int nc = 0;
            #pragma unroll
            for (int dzb = -1; dzb <= 1; dzb++) {
                int Z = bz + dzb;
                if (Z < 0 || Z >= NBZ) continue;
                #pragma unroll
                for (int dyb = -1; dyb <= 1; dyb++) {
                    int Y = by + dyb;
                    if (Y < 0 || Y >= NBX) continue;
                    int row = (Z * NBX + Y) * NBX;
                    unsigned st = binStart[row + x0];
                    unsigned en = binStart[row + x1] + binCnt[row + x1];
                    for (unsigned p = st; p < en; p++) {
                        int a = binPts[p];
                        if (a < ci) {
                            float d2 = dist2(px, py, pz, cx[a], cy[a], cz[a]);
                            if (d2 < dd && nc < NNCAP)
                                nbr[ci * NNCAP + nc++] = (unsigned short)a;
                        }
                    }
                }
            }
            nbrCnt[ci] = (unsigned char)nc;
            int st0 = (nc == 0) ? 1 : 0;
            state[ci] = (unsigned char)st0;
            undec += (st0 == 0);
        }
        if (undec) atomicAdd(&remaining, undec);
    }
    __syncthreads();

    // ---- wave NMS resolution (exact sequential semantics) ----
    while (true) {
        if (remaining <= 0) break;
        int dec = 0;
        for (int ci = tid; ci < m; ci += NTH) {
            if (state[ci] == 0) {
                int nc = nbrCnt[ci];
                bool anyK = false, allS = true;
                for (int k2 = 0; k2 < nc; k2++) {
                    unsigned char s2 = state[nbr[ci * NNCAP + k2]];
                    if (s2 == 1) { anyK = true; break; }
                    allS &= (s2 == 2);
                }
                if (anyK) { state[ci] = 2; dec++; }
                else if (allS) { state[ci] = 1; dec++; }
            }
        }
        if (dec) atomicSub(&remaining, dec);
        __syncthreads();
    }

    // ---- keep mask scatter ----
    for (int ci = tid; ci < m; ci += NTH)
        fullk[spos[ci]] = (state[ci] == 1) ? 1 : 0;

    // ---- order-preserving compaction of kept -> g_k* ----
    {
        int base2 = tid * 2;
        int k0 = (base2 < m) ? (state[base2] == 1) : 0;
        int k1 = (base2 + 1 < m) ? (state[base2 + 1] == 1) : 0;
        int ex2 = blockScanExcl(k0 + k1, wsum, tid);   // barrier fences fullk scatter too
        int kc = wsum[31];
        int kb2 = prob * 2048;
        if (k0) {
            g_kx[kb2 + ex2] = cx[base2]; g_ky[kb2 + ex2] = cy[base2];
            g_kz[kb2 + ex2] = cz[base2]; g_kpos[kb2 + ex2] = spos[base2];
            ex2++;
        }
        if (k1) {
            g_kx[kb2 + ex2] = cx[base2 + 1]; g_ky[kb2 + ex2] = cy[base2 + 1];
            g_kz[kb2 + ex2] = cz[base2 + 1]; g_kpos[kb2 + ex2] = spos[base2 + 1];
        }
        if (tid == 0) g_kcnt[prob] = kc;
    }

    // ---- write keep mask ----
    int kb = (t ? OFF_KT : OFF_KP) + (b * 2 + e) * 4096;
    for (int q = 0; q < 4; q++) {
        int s = tid * 4 + q;
        out[kb + s] = (float)fullk[s];
    }
}

// ---------------------------------------------------------------------------
// Kernel D (8 blocks): matching; candidate build uses x-range scan
// ---------------------------------------------------------------------------
__global__ void __launch_bounds__(1024) k_match(float* __restrict__ out)
{
    extern __shared__ unsigned char sm[];
    float* cpx = (float*)sm;
    float* cpy = (float*)(sm + 8 * 1024);
    float* cpz = (float*)(sm + 16 * 1024);
    float* ctx = (float*)(sm + 24 * 1024);
    float* cty = (float*)(sm + 32 * 1024);
    float* ctz = (float*)(sm + 40 * 1024);
    unsigned short* ppos = (unsigned short*)(sm + 48 * 1024);
    unsigned short* tpos = (unsigned short*)(sm + 52 * 1024);
    unsigned int* binCnt = (unsigned int*)(sm + 56 * 1024);
    unsigned int* binStart = (unsigned int*)(sm + 88 * 1024);
    unsigned short* binPts = (unsigned short*)(sm + 120 * 1024);
    unsigned char* candCnt = (unsigned char*)(sm + 124 * 1024);
    unsigned short* cand = (unsigned short*)(sm + 126 * 1024);
    unsigned char* tpF = (unsigned char*)(sm + 174 * 1024);
    unsigned char* mtF = (unsigned char*)(sm + 178 * 1024);
    unsigned int* taken = (unsigned int*)(sm + 182 * 1024);
    unsigned int* minIdx = (unsigned int*)(sm + 56 * 1024);    // alias binCnt
    unsigned short* actA = (unsigned short*)(sm + 88 * 1024);  // alias binStart
    unsigned short* actB = (unsigned short*)(sm + 92 * 1024);

    __shared__ int wsum[32];
    __shared__ int nact, nNext;

    const int tid = threadIdx.x;
    const int be = blockIdx.x;
    const int b = be >> 1, e = be & 1;
    const float de = (e == 0) ? (float)(0.74 * 1.4) : (float)(0.528 * 1.4);
    const float dd = __fmul_rn(de, de);
    const float cellXY = fmaxf(de, 1.02f);
    const float invXY = 1.0f / cellXY;
    const float invZ = 1.0f / 1.3125f;

    const int kpBase = OFF_KP + (b * 2 + e) * 4096;
    const int ktBase = OFF_KT + (b * 2 + e) * 4096;
    const int pP = be, pT = 8 + be;

    const int KP = min(g_kcnt[pP], 2048);
    const int KT = min(g_kcnt[pT], 2048);

    for (int i = tid; i < KP; i += NTH) {
        cpx[i] = g_kx[pP * 2048 + i];
        cpy[i] = g_ky[pP * 2048 + i];
        cpz[i] = g_kz[pP * 2048 + i];
        ppos[i] = g_kpos[pP * 2048 + i];
    }
    for (int i = tid; i < KT; i += NTH) {
        ctx[i] = g_kx[pT * 2048 + i];
        cty[i] = g_ky[pT * 2048 + i];
        ctz[i] = g_kz[pT * 2048 + i];
        tpos[i] = g_kpos[pT * 2048 + i];
    }
    for (int i = tid; i < NBX * NBX * NBZ; i += NTH) binCnt[i] = 0;
    if (tid < 64) taken[tid] = 0u;
    if (tid == 0) { nact = 0; nNext = 0; }
    for (int q = 0; q < 4; q++) { tpF[tid * 4 + q] = 0; mtF[tid * 4 + q] = 0; }
    __syncthreads();

    // ---- bin kept targets ----
    for (int ci = tid; ci < KT; ci += NTH) {
        int bx, by, bz;
        binCoords(ctx[ci], cty[ci], ctz[ci], invXY, invZ, bx, by, bz);
        atomicAdd(&binCnt[(bz * NBX + by) * NBX + bx], 1u);
    }
    __syncthreads();
    {
        int base8 = tid * 8;
        int loc[8]; int s = 0;
        for (int k2 = 0; k2 < 8; k2++) { loc[k2] = s; s += (int)binCnt[base8 + k2]; }
        int ex = blockScanExcl(s, wsum, tid);
        for (int k2 = 0; k2 < 8; k2++) binStart[base8 + k2] = (unsigned)(ex + loc[k2]);
    }
    __syncthreads();
    for (int i = tid; i < NBX * NBX * NBZ; i += NTH) binCnt[i] = 0;
    __syncthreads();
    for (int ci = tid; ci < KT; ci += NTH) {
        int bx, by, bz;
        binCoords(ctx[ci], cty[ci], ctz[ci], invXY, invZ, bx, by, bz);
        int bb = (bz * NBX + by) * NBX + bx;
        unsigned off = atomicAdd(&binCnt[bb], 1u);
        binPts[binStart[bb] + off] = (unsigned short)ci;
    }
    __syncthreads();

    // ---- per-pred sorted candidate lists (contiguous x-range scan) ----
    for (int ci = tid; ci < KP; ci += NTH) {
        float px = cpx[ci], py = cpy[ci], pz = cpz[ci];
        int bx, by, bz;
        binCoords(px, py, pz, invXY, invZ, bx, by, bz);
        int x0 = bx > 0 ? bx - 1 : 0;
        int x1 = bx < NBX - 1 ? bx + 1 : NBX - 1;
        unsigned short* cl = cand + ci * CAP;
        int nc = 0;
        #pragma unroll
        for (int dzb = -1; dzb <= 1; dzb++) {
            int Z = bz + dzb;
            if (Z < 0 || Z >= NBZ) continue;
            #pragma unroll
            for (int dyb = -1; dyb <= 1; dyb++) {
                int Y = by + dyb;
                if (Y < 0 || Y >= NBX) continue;
                int row = (Z * NBX + Y) * NBX;
                unsigned st = binStart[row + x0];
                unsigned en = binStart[row + x1] + binCnt[row + x1];
                for (unsigned p = st; p < en; p++) {
                    int a = binPts[p];
                    float d2 = dist2(px, py, pz, ctx[a], cty[a], ctz[a]);
                    if (d2 < dd) {
                        if (nc < CAP) {
                            int k2 = nc;
                            while (k2 > 0 && cl[k2 - 1] > a) { cl[k2] = cl[k2 - 1]; k2--; }
                            cl[k2] = (unsigned short)a;
                            nc++;
                        } else if (a < cl[CAP - 1]) {
                            int k2 = CAP - 1;
                            while (k2 > 0 && cl[k2 - 1] > a) { cl[k2] = cl[k2 - 1]; k2--; }
                            cl[k2] = (unsigned short)a;
                        }
                    }
                }
            }
        }
        candCnt[ci] = (unsigned char)nc;
    }
    __syncthreads();     // bins dead; actA/actB alias binStart region

    // ---- initial active list ----
    for (int i = tid; i < KP; i += NTH) {
        if (candCnt[i] > 0) {
            int p = atomicAdd(&nact, 1);
            actA[p] = (unsigned short)i;
        }
    }
    int parity = 0;

    // ---- active-list wave resolution (exact sequential semantics) ----
    while (true) {
        __syncthreads();
        int na = nact;
        if (na <= 0) break;
        const unsigned short* A = parity ? actB : actA;
        unsigned short* Bn = parity ? actA : actB;

        for (int idx = tid; idx < na; idx += NTH) {
            int i = A[idx];
            int nc = candCnt[i];
            const unsigned short* cl = cand + i * CAP;
            for (int k2 = 0; k2 < nc; k2++) minIdx[cl[k2]] = 0x7FFFFFFFu;
        }
        if (tid == 0) nNext = 0;
        __syncthreads();
        for (int idx = tid; idx < na; idx += NTH) {
            int i = A[idx];
            int nc = candCnt[i];
            const unsigned short* cl = cand + i * CAP;
            for (int k2 = 0; k2 < nc; k2++)
                atomicMin(&minIdx[cl[k2]], (unsigned)i);
        }
        __syncthreads();
        for (int idx = tid; idx < na; idx += NTH) {
            int i = A[idx];
            int nc = candCnt[i];
            const unsigned short* cl = cand + i * CAP;
            bool ok = true;
            for (int k2 = 0; k2 < nc; k2++)
                if (minIdx[cl[k2]] < (unsigned)i) { ok = false; break; }
            if (ok) {
                for (int k2 = 0; k2 < nc; k2++) {
                    int j = cl[k2];
                    if (!((taken[j >> 5] >> (j & 31)) & 1u)) {
                        atomicOr(&taken[j >> 5], 1u << (j & 31));
                        tpF[ppos[i]] = 1;
                        mtF[tpos[j]] = 1;
                        break;
                    }
                }
            } else {
                int p = atomicAdd(&nNext, 1);
                Bn[p] = (unsigned short)i;
            }
        }
        __syncthreads();
        if (tid == 0) nact = nNext;
        parity ^= 1;
    }

    // ---- write tp/fp/fn ----
    const int tpB = OFF_TP + (b * 2 + e) * 4096;
    const int fpB = OFF_FP + (b * 2 + e) * 4096;
    const int fnB = OFF_FN + (b * 2 + e) * 4096;
    for (int q = 0; q < 4; q++) {
        int s = tid * 4 + q;
        int tp = tpF[s];
        int kp = (out[kpBase + s] > 0.5f) ? 1 : 0;
        int kt = (out[ktBase + s] > 0.5f) ? 1 : 0;
        out[tpB + s] = (float)tp;
        out[fpB + s] = (kp && !tp) ? 1.0f : 0.0f;
        out[fnB + s] = (kt && !mtF[s]) ? 1.0f : 0.0f;
    }
}

// ---------------------------------------------------------------------------
extern "C" void kernel_launch(void* const* d_in, const int* in_sizes, int n_in,
                              void* d_out, int out_size)
{
    const float* pred = (const float*)d_in[0];
    const float* targ = (const float*)d_in[1];
    float* out = (float*)d_out;

    cudaFuncSetAttribute(k_nms2, cudaFuncAttributeMaxDynamicSharedMemorySize, 168 * 1024);
    cudaFuncSetAttribute(k_match, cudaFuncAttributeMaxDynamicSharedMemorySize, 184 * 1024);

    k_sortA<<<64, NTH, 8 * 1024>>>(pred, targ);
    k_sortB<<<32, NTH, 16 * 1024>>>();
    k_coords<<<32, NTH, 32 * 1024>>>(pred, targ, out);
    k_nms2<<<16, NTH, 168 * 1024>>>(out);
    k_match<<<8, NTH, 184 * 1024>>>(out);
}

// round 13
// speedup vs baseline: 2.4085x; 1.0059x over previous
#include <cuda_runtime.h>
#include <cstdint>

#define NPTS 4096
#define NTH  1024

// d_out float32 layout:
//   Pc [4][2][4096][3] @0, Tc @98304, keepP @196608, keepT @229376,
//   tp @262144, fp @294912, fn @327680
#define OFF_TC 98304
#define OFF_KP 196608
#define OFF_KT 229376
#define OFF_TP 262144
#define OFF_FP 294912
#define OFF_FN 327680

#define NBX 32
#define NBZ 8
#define CAP 12
#define NNCAP 16
#define MAXV 2048

__device__ unsigned long long g_run0[16 * 4096];
__device__ unsigned long long g_run1[16 * 4096];
// per-half compacted valid points (sorted order preserved)
__device__ float g_vx[16 * 4096];
__device__ float g_vy[16 * 4096];
__device__ float g_vz[16 * 4096];
__device__ unsigned short g_vs[16 * 4096];   // sorted position 0..4095
__device__ int g_vcnt[32];
// NMS-kept compact lists per problem
__device__ float g_kx[16 * 2048];
__device__ float g_ky[16 * 2048];
__device__ float g_kz[16 * 2048];
__device__ unsigned short g_kpos[16 * 2048];
__device__ int g_kcnt[16];

__device__ __forceinline__ float dist2(float ax, float ay, float az,
                                       float bx, float by, float bz) {
    float dx = __fadd_rn(ax, -bx);
    float dy = __fadd_rn(ay, -by);
    float dz = __fadd_rn(az, -bz);
    return __fadd_rn(__fadd_rn(__fmul_rn(dx, dx), __fmul_rn(dy, dy)),
                     __fmul_rn(dz, dz));
}

__device__ __forceinline__ int clampi(int v, int lo, int hi) {
    return v < lo ? lo : (v > hi ? hi : v);
}

__device__ __forceinline__ void binCoords(float x, float y, float z,
                                          float invXY, float invZ,
                                          int& bx, int& by, int& bz) {
    bx = clampi((int)floorf(__fmul_rn(__fadd_rn(x, 4.5f), invXY)), 0, NBX - 1);
    by = clampi((int)floorf(__fmul_rn(__fadd_rn(y, 4.5f), invXY)), 0, NBX - 1);
    bz = clampi((int)floorf(__fmul_rn(__fadd_rn(z, 4.0f), invZ)),  0, NBZ - 1);
}

__device__ __forceinline__ int blockScanExcl(int cnt, int* wsum, int tid) {
    int lane = tid & 31, wid = tid >> 5;
    int v = cnt;
    for (int o = 1; o < 32; o <<= 1) {
        int nn = __shfl_up_sync(0xFFFFFFFFu, v, o);
        if (lane >= o) v += nn;
    }
    if (lane == 31) wsum[wid] = v;
    __syncthreads();
    if (wid == 0) {
        int w = wsum[lane];
        for (int o = 1; o < 32; o <<= 1) {
            int nn = __shfl_up_sync(0xFFFFFFFFu, w, o);
            if (lane >= o) w += nn;
        }
        wsum[lane] = w;
    }
    __syncthreads();
    return v - cnt + (wid ? wsum[wid - 1] : 0);
}

// ---------------------------------------------------------------------------
// Kernel A (64 blocks): sort 1024-key runs -> g_run0
// ---------------------------------------------------------------------------
__global__ void __launch_bounds__(1024) k_sortA(const float* __restrict__ pred,
                                                const float* __restrict__ targ)
{
    extern __shared__ unsigned char sm[];
    unsigned long long* s = (unsigned long long*)sm;   // [1024]
    const int tid = threadIdx.x;
    const int bi = blockIdx.x;
    const int prob = bi >> 2;
    const int quarter = bi & 3;
    const int t = prob >> 3;
    const int be = prob & 7;
    const int b = be >> 1;
    const int e = be & 1;
    const float* in = (t == 0) ? pred : targ;

    int n = quarter * 1024 + tid;
    int z = n >> 10, x = (n >> 5) & 31, y = n & 31;
    int base = ((((b * 32 + x) * 32 + y) * 4 + z) * 8) + e * 4;
    float conf = in[base + 3];
    unsigned u = __float_as_uint(conf);
    u = (u & 0x80000000u) ? ~u : (u | 0x80000000u);
    unsigned long long v = (((unsigned long long)(~u)) << 32) | (unsigned)n;

    for (int k = 2; k <= 1024; k <<= 1) {
        bool up = ((tid & k) == 0);
        for (int j = k >> 1; j > 0; j >>= 1) {
            unsigned long long p;
            if (j >= 32) {
                s[tid] = v;
                __syncthreads();
                p = s[tid ^ j];
                __syncthreads();
            } else {
                p = __shfl_xor_sync(0xFFFFFFFFu, v, j);
            }
            bool lower = ((tid & j) == 0);
            bool kmin = (lower == up);
            unsigned long long mn = v < p ? v : p;
            unsigned long long mx = v < p ? p : v;
            v = kmin ? mn : mx;
        }
    }
    g_run0[prob * 4096 + quarter * 1024 + tid] = v;
}

// ---------------------------------------------------------------------------
// Kernel B (32 blocks): merge 1024+1024 -> 2048 -> g_run1
// ---------------------------------------------------------------------------
__global__ void __launch_bounds__(1024) k_sortB()
{
    extern __shared__ unsigned char sm[];
    unsigned long long* sA = (unsigned long long*)sm;              // [1024]
    unsigned long long* sB = (unsigned long long*)(sm + 8 * 1024); // [1024]
    const int tid = threadIdx.x;
    const int prob = blockIdx.x >> 1;
    const int half = blockIdx.x & 1;
    const unsigned long long* src = g_run0 + prob * 4096 + half * 2048;
    sA[tid] = src[tid];
    sB[tid] = src[1024 + tid];
    __syncthreads();

    int diag = tid * 2;
    int lo = diag > 1024 ? diag - 1024 : 0;
    int hi = diag < 1024 ? diag : 1024;
    while (lo < hi) {
        int mid = (lo + hi) >> 1;
        if (sA[mid] < sB[diag - 1 - mid]) lo = mid + 1; else hi = mid;
    }
    int ai = lo, bj = diag - lo;
    unsigned long long* dst = g_run1 + prob * 4096 + half * 2048;
    #pragma unroll
    for (int r = 0; r < 2; r++) {
        bool takeA = (bj >= 1024) || (ai < 1024 && sA[ai] <= sB[bj]);
        dst[diag + r] = takeA ? sA[ai++] : sB[bj++];
    }
}

// ---------------------------------------------------------------------------
// Kernel C1 (32 blocks, 2/problem): merge-path half -> coords -> Pc/Tc
//   + per-half order-preserving valid compaction -> g_v*
// ---------------------------------------------------------------------------
__global__ void __launch_bounds__(1024) k_coords(const float* __restrict__ pred,
                                                 const float* __restrict__ targ,
                                                 float* __restrict__ out)
{
    extern __shared__ unsigned char sm[];
    unsigned long long* sA2 = (unsigned long long*)sm;             // [2048] 16KB
    unsigned long long* sB2 = (unsigned long long*)(sm + 16 * 1024);
    __shared__ int wsum[32];

    const int tid = threadIdx.x;
    const int bi = blockIdx.x;
    const int prob = bi >> 1;
    const int half = bi & 1;
    const int t = prob >> 3;
    const int be = prob & 7;
    const int b = be >> 1;
    const int e = be & 1;
    const float* in = (t == 0) ? pred : targ;

    {
        const unsigned long long* src = g_run1 + prob * 4096;
        sA2[tid] = src[tid];
        sA2[1024 + tid] = src[1024 + tid];
        sB2[tid] = src[2048 + tid];
        sB2[1024 + tid] = src[3072 + tid];
    }
    __syncthreads();

    const int diag = half * 2048 + tid * 2;
    int lo = diag > 2048 ? diag - 2048 : 0;
    int hi = diag < 2048 ? diag : 2048;
    while (lo < hi) {
        int mid = (lo + hi) >> 1;
        if (sA2[mid] < sB2[diag - 1 - mid]) lo = mid + 1; else hi = mid;
    }
    int ai = lo, bj = diag - lo;
    unsigned long long myk[2];
    #pragma unroll
    for (int r = 0; r < 2; r++) {
        bool takeA = (bj >= 2048) || (ai < 2048 && sA2[ai] <= sB2[bj]);
        myk[r] = takeA ? sA2[ai++] : sB2[bj++];
    }

    float rx[2], ry[2], rz[2];
    int vf[2]; int cnt = 0;
    #pragma unroll
    for (int q = 0; q < 2; q++) {
        int n = (int)(myk[q] & 0xFFFFFFFFull);
        int z = n >> 10, x = (n >> 5) & 31, y = n & 31;
        int base = ((((b * 32 + x) * 32 + y) * 4 + z) * 8) + e * 4;
        float4 vv = *(const float4*)(in + base);
        float c0 = __fmul_rn(__fadd_rn(vv.z, (float)z), 0.75f);
        float c1 = __fmul_rn(__fadd_rn(vv.x, (float)x), 0.78125f);
        float c2 = __fmul_rn(__fadd_rn(vv.y, (float)y), 0.78125f);
        rx[q] = c0; ry[q] = c1; rz[q] = c2;
        vf[q] = (vv.w > 0.5f) ? 1 : 0;
        cnt += vf[q];
        int s = diag + q;
        int ob = (t ? OFF_TC : 0) + ((b * 2 + e) * 4096 + s) * 3;
        out[ob + 0] = c0; out[ob + 1] = c1; out[ob + 2] = c2;
    }

    int excl = blockScanExcl(cnt, wsum, tid);
    int gb = prob * 4096 + half * 2048;
    #pragma unroll
    for (int q = 0; q < 2; q++) {
        if (vf[q]) {
            g_vx[gb + excl] = rx[q];
            g_vy[gb + excl] = ry[q];
            g_vz[gb + excl] = rz[q];
            g_vs[gb + excl] = (unsigned short)(diag + q);
            excl++;
        }
    }
    if (tid == 0) g_vcnt[bi] = wsum[31];
}

// ---------------------------------------------------------------------------
// Kernel C2 (16 blocks): stitch -> bins -> neighbor lists (x-range scan)
//   -> BARRIER-FREE wave NMS fixpoint -> keep masks + kept lists
// ---------------------------------------------------------------------------
__global__ void __launch_bounds__(1024) k_nms2(float* __restrict__ out)
{
    extern __shared__ unsigned char sm[];
    float* cx = (float*)sm;                                      // 8KB
    float* cy = (float*)(sm + 8 * 1024);
    float* cz = (float*)(sm + 16 * 1024);
    unsigned short* spos = (unsigned short*)(sm + 24 * 1024);    // 4KB
    unsigned char* fullk = (unsigned char*)(sm + 28 * 1024);     // 4KB
    unsigned short* nbr = (unsigned short*)(sm + 32 * 1024);     // 64KB
    unsigned int* binCnt = (unsigned int*)(sm + 96 * 1024);      // 32KB
    unsigned int* binStart = (unsigned int*)(sm + 128 * 1024);   // 32KB
    unsigned short* binPts = (unsigned short*)(sm + 160 * 1024); // 4KB
    unsigned char* nbrCnt = (unsigned char*)(sm + 164 * 1024);   // 2KB
    unsigned char* state = (unsigned char*)(sm + 166 * 1024);    // 2KB

    __shared__ int wsum[32];

    const int tid = threadIdx.x;
    const int prob = blockIdx.x;
    const int t = prob >> 3;
    const int be = prob & 7;
    const int b = be >> 1;
    const int e = be & 1;
    const float de = (e == 0) ? (float)(0.74 * 1.4) : (float)(0.528 * 1.4);
    const float dd = __fmul_rn(de, de);
    const float cellXY = fmaxf(de, 1.02f);
    const float invXY = 1.0f / cellXY;
    const float invZ = 1.0f / 1.3125f;

    const int c0 = min(g_vcnt[prob * 2], MAXV);
    const int c1 = g_vcnt[prob * 2 + 1];
    const int m = min(c0 + c1, MAXV);
    const int gb = prob * 4096;

    // stitch halves (order-preserving: half0 then half1)
    for (int i = tid; i < c0; i += NTH) {
        cx[i] = g_vx[gb + i]; cy[i] = g_vy[gb + i]; cz[i] = g_vz[gb + i];
        spos[i] = g_vs[gb + i];
    }
    for (int i = tid; i < m - c0; i += NTH) {
        cx[c0 + i] = g_vx[gb + 2048 + i];
        cy[c0 + i] = g_vy[gb + 2048 + i];
        cz[c0 + i] = g_vz[gb + 2048 + i];
        spos[c0 + i] = g_vs[gb + 2048 + i];
    }
    for (int i = tid; i < NBX * NBX * NBZ; i += NTH) binCnt[i] = 0;
    for (int q = 0; q < 4; q++) fullk[tid * 4 + q] = 0;
    __syncthreads();

    // ---- bins ----
    for (int ci = tid; ci < m; ci += NTH) {
        int bx, by, bz;
        binCoords(cx[ci], cy[ci], cz[ci], invXY, invZ, bx, by, bz);
        atomicAdd(&binCnt[(bz * NBX + by) * NBX + bx], 1u);
    }
    __syncthreads();
    {
        int base8 = tid * 8;
        int loc[8]; int s = 0;
        for (int k2 = 0; k2 < 8; k2++) { loc[k2] = s; s += (int)binCnt[base8 + k2]; }
        int ex = blockScanExcl(s, wsum, tid);
        for (int k2 = 0; k2 < 8; k2++) binStart[base8 + k2] = (unsigned)(ex + loc[k2]);
    }
    __syncthreads();
    for (int i = tid; i < NBX * NBX * NBZ; i += NTH) binCnt[i] = 0;
    __syncthreads();
    for (int ci = tid; ci < m; ci += NTH) {
        int bx, by, bz;
        binCoords(cx[ci], cy[ci], cz[ci], invXY, invZ, bx, by, bz);
        int bb = (bz * NBX + by) * NBX + bx;
        unsigned off = atomicAdd(&binCnt[bb], 1u);
        binPts[binStart[bb] + off] = (unsigned short)ci;
    }
    __syncthreads();

    // ---- one-pass earlier-neighbor lists (contiguous x-range scan) ----
    for (int ci = tid; ci < m; ci += NTH) {
        float px = cx[ci], py = cy[ci], pz = cz[ci];
        int bx, by, bz;
        binCoords(px, py, pz, invXY, invZ, bx, by, bz);
        int x0 = bx > 0 ? bx - 1 : 0;
        int x1 = bx < NBX - 1 ? bx + 1 : NBX - 1;
        int nc = 0;
        #pragma unroll
        for (int dzb = -1; dzb <= 1; dzb++) {
            int Z = bz + dzb;
            if (Z < 0 || Z >= NBZ) continue;
            #pragma unroll
            for (int dyb = -1; dyb <= 1; dyb++) {
                int Y = by + dyb;
                if (Y < 0 || Y >= NBX) continue;
                int row = (Z * NBX + Y) * NBX;
                unsigned st = binStart[row + x0];
                unsigned en = binStart[row + x1] + binCnt[row + x1];
                for (unsigned p = st; p < en; p++) {
                    int a = binPts[p];
                    if (a < ci) {
                        float d2 = dist2(px, py, pz, cx[a], cy[a], cz[a]);
                        if (d2 < dd && nc < NNCAP)
                            nbr[ci * NNCAP + nc++] = (unsigned short)a;
                    }
                }
            }
        }
        nbrCnt[ci] = (unsigned char)nc;
        state[ci] = (nc == 0) ? (unsigned char)1 : (unsigned char)0;
    }
    __syncthreads();   // all initial states + nbr lists visible

    // ---- BARRIER-FREE wave NMS fixpoint ----
    // States are monotone (0 -> 1 kept | 2 suppressed) and the recurrence is
    // confluent (keep[j] = no earlier kept neighbor; earlier = lower index).
    // The smallest undecided point is always decidable, and its owner thread
    // is still spinning => no deadlock. Volatile smem gives intra-block
    // visibility without barriers.
    {
        volatile unsigned char* vst = (volatile unsigned char*)state;
        int p0 = tid, p1 = tid + NTH;
        bool d0 = (p0 >= m) || (state[p0] != 0);
        bool d1 = (p1 >= m) || (state[p1] != 0);
        while (!(d0 && d1)) {
            if (!d0) {
                int nc = nbrCnt[p0];
                const unsigned short* nl = nbr + p0 * NNCAP;
                bool anyK = false, allS = true;
                for (int k2 = 0; k2 < nc; k2++) {
                    unsigned char s2 = vst[nl[k2]];
                    if (s2 == 1) { anyK = true; break; }
                    allS &= (s2 == 2);
                }
                if (anyK) { vst[p0] = 2; d0 = true; }
                else if (allS) { vst[p0] = 1; d0 = true; }
            }
            if (!d1) {
                int nc = nbrCnt[p1];
                const unsigned short* nl = nbr + p1 * NNCAP;
                bool anyK = false, allS = true;
                for (int k2 = 0; k2 < nc; k2++) {
                    unsigned char s2 = vst[nl[k2]];
                    if (s2 == 1) { anyK = true; break; }
                    allS &= (s2 == 2);
                }
                if (anyK) { vst[p1] = 2; d1 = true; }
                else if (allS) { vst[p1] = 1; d1 = true; }
            }
        }
    }
    __syncthreads();

    // ---- keep mask scatter ----
    for (int ci = tid; ci < m; ci += NTH)
        fullk[spos[ci]] = (state[ci] == 1) ? 1 : 0;

    // ---- order-preserving compaction of kept -> g_k* ----
    {
        int base2 = tid * 2;
        int k0 = (base2 < m) ? (state[base2] == 1) : 0;
        int k1 = (base2 + 1 < m) ? (state[base2 + 1] == 1) : 0;
        int ex2 = blockScanExcl(k0 + k1, wsum, tid);   // barrier fences fullk scatter too
        int kc = wsum[31];
        int kb2 = prob * 2048;
        if (k0) {
            g_kx[kb2 + ex2] = cx[base2]; g_ky[kb2 + ex2] = cy[base2];
            g_kz[kb2 + ex2] = cz[base2]; g_kpos[kb2 + ex2] = spos[base2];
            ex2++;
        }
        if (k1) {
            g_kx[kb2 + ex2] = cx[base2 + 1]; g_ky[kb2 + ex2] = cy[base2 + 1];
            g_kz[kb2 + ex2] = cz[base2 + 1]; g_kpos[kb2 + ex2] = spos[base2 + 1];
        }
        if (tid == 0) g_kcnt[prob] = kc;
    }

    // ---- write keep mask ----
    int kb = (t ? OFF_KT : OFF_KP) + (b * 2 + e) * 4096;
    for (int q = 0; q < 4; q++) {
        int s = tid * 4 + q;
        out[kb + s] = (float)fullk[s];
    }
}

// ---------------------------------------------------------------------------
// Kernel D (8 blocks): matching; candidate build uses x-range scan
// ---------------------------------------------------------------------------
__global__ void __launch_bounds__(1024) k_match(float* __restrict__ out)
{
    extern __shared__ unsigned char sm[];
    float* cpx = (float*)sm;
    float* cpy = (float*)(sm + 8 * 1024);
    float* cpz = (float*)(sm + 16 * 1024);
    float* ctx = (float*)(sm + 24 * 1024);
    float* cty = (float*)(sm + 32 * 1024);
    float* ctz = (float*)(sm + 40 * 1024);
    unsigned short* ppos = (unsigned short*)(sm + 48 * 1024);
    unsigned short* tpos = (unsigned short*)(sm + 52 * 1024);
    unsigned int* binCnt = (unsigned int*)(sm + 56 * 1024);
    unsigned int* binStart = (unsigned int*)(sm + 88 * 1024);
    unsigned short* binPts = (unsigned short*)(sm + 120 * 1024);
    unsigned char* candCnt = (unsigned char*)(sm + 124 * 1024);
    unsigned short* cand = (unsigned short*)(sm + 126 * 1024);
    unsigned char* tpF = (unsigned char*)(sm + 174 * 1024);
    unsigned char* mtF = (unsigned char*)(sm + 178 * 1024);
    unsigned int* taken = (unsigned int*)(sm + 182 * 1024);
    unsigned int* minIdx = (unsigned int*)(sm + 56 * 1024);    // alias binCnt
    unsigned short* actA = (unsigned short*)(sm + 88 * 1024);  // alias binStart
    unsigned short* actB = (unsigned short*)(sm + 92 * 1024);

    __shared__ int wsum[32];
    __shared__ int nact, nNext;

    const int tid = threadIdx.x;
    const int be = blockIdx.x;
    const int b = be >> 1, e = be & 1;
    const float de = (e == 0) ? (float)(0.74 * 1.4) : (float)(0.528 * 1.4);
    const float dd = __fmul_rn(de, de);
    const float cellXY = fmaxf(de, 1.02f);
    const float invXY = 1.0f / cellXY;
    const float invZ = 1.0f / 1.3125f;

    const int kpBase = OFF_KP + (b * 2 + e) * 4096;
    const int ktBase = OFF_KT + (b * 2 + e) * 4096;
    const int pP = be, pT = 8 + be;

    const int KP = min(g_kcnt[pP], 2048);
    const int KT = min(g_kcnt[pT], 2048);

    for (int i = tid; i < KP; i += NTH) {
        cpx[i] = g_kx[pP * 2048 + i];
        cpy[i] = g_ky[pP * 2048 + i];
        cpz[i] = g_kz[pP * 2048 + i];
        ppos[i] = g_kpos[pP * 2048 + i];
    }
    for (int i = tid; i < KT; i += NTH) {
        ctx[i] = g_kx[pT * 2048 + i];
        cty[i] = g_ky[pT * 2048 + i];
        ctz[i] = g_kz[pT * 2048 + i];
        tpos[i] = g_kpos[pT * 2048 + i];
    }
    for (int i = tid; i < NBX * NBX * NBZ; i += NTH) binCnt[i] = 0;
    if (tid < 64) taken[tid] = 0u;
    if (tid == 0) { nact = 0; nNext = 0; }
    for (int q = 0; q < 4; q++) { tpF[tid * 4 + q] = 0; mtF[tid * 4 + q] = 0; }
    __syncthreads();

    // ---- bin kept targets ----
    for (int ci = tid; ci < KT; ci += NTH) {
        int bx, by, bz;
        binCoords(ctx[ci], cty[ci], ctz[ci], invXY, invZ, bx, by, bz);
        atomicAdd(&binCnt[(bz * NBX + by) * NBX + bx], 1u);
    }
    __syncthreads();
    {
        int base8 = tid * 8;
        int loc[8]; int s = 0;
        for (int k2 = 0; k2 < 8; k2++) { loc[k2] = s; s += (int)binCnt[base8 + k2]; }
        int ex = blockScanExcl(s, wsum, tid);
        for (int k2 = 0; k2 < 8; k2++) binStart[base8 + k2] = (unsigned)(ex + loc[k2]);
    }
    __syncthreads();
    for (int i = tid; i < NBX * NBX * NBZ; i += NTH) binCnt[i] = 0;
    __syncthreads();
    for (int ci = tid; ci < KT; ci += NTH) {
        int bx, by, bz;
        binCoords(ctx[ci], cty[ci], ctz[ci], invXY, invZ, bx, by, bz);
        int bb = (bz * NBX + by) * NBX + bx;
        unsigned off = atomicAdd(&binCnt[bb], 1u);
        binPts[binStart[bb] + off] = (unsigned short)ci;
    }
    __syncthreads();

    // ---- per-pred sorted candidate lists (contiguous x-range scan) ----
    for (int ci = tid; ci < KP; ci += NTH) {
        float px = cpx[ci], py = cpy[ci], pz = cpz[ci];
        int bx, by, bz;
        binCoords(px, py, pz, invXY, invZ, bx, by, bz);
        int x0 = bx > 0 ? bx - 1 : 0;
        int x1 = bx < NBX - 1 ? bx + 1 : NBX - 1;
        unsigned short* cl = cand + ci * CAP;
        int nc = 0;
        #pragma unroll
        for (int dzb = -1; dzb <= 1; dzb++) {
            int Z = bz + dzb;
            if (Z < 0 || Z >= NBZ) continue;
            #pragma unroll
            for (int dyb = -1; dyb <= 1; dyb++) {
                int Y = by + dyb;
                if (Y < 0 || Y >= NBX) continue;
                int row = (Z * NBX + Y) * NBX;
                unsigned st = binStart[row + x0];
                unsigned en = binStart[row + x1] + binCnt[row + x1];
                for (unsigned p = st; p < en; p++) {
                    int a = binPts[p];
                    float d2 = dist2(px, py, pz, ctx[a], cty[a], ctz[a]);
                    if (d2 < dd) {
                        if (nc < CAP) {
                            int k2 = nc;
                            while (k2 > 0 && cl[k2 - 1] > a) { cl[k2] = cl[k2 - 1]; k2--; }
                            cl[k2] = (unsigned short)a;
                            nc++;
                        } else if (a < cl[CAP - 1]) {
                            int k2 = CAP - 1;
                            while (k2 > 0 && cl[k2 - 1] > a) { cl[k2] = cl[k2 - 1]; k2--; }
                            cl[k2] = (unsigned short)a;
                        }
                    }
                }
            }
        }
        candCnt[ci] = (unsigned char)nc;
    }
    __syncthreads();     // bins dead; actA/actB alias binStart region

    // ---- initial active list ----
    for (int i = tid; i < KP; i += NTH) {
        if (candCnt[i] > 0) {
            int p = atomicAdd(&nact, 1);
            actA[p] = (unsigned short)i;
        }
    }
    int parity = 0;

    // ---- active-list wave resolution (exact sequential semantics) ----
    while (true) {
        __syncthreads();
        int na = nact;
        if (na <= 0) break;
        const unsigned short* A = parity ? actB : actA;
        unsigned short* Bn = parity ? actA : actB;

        for (int idx = tid; idx < na; idx += NTH) {
            int i = A[idx];
            int nc = candCnt[i];
            const unsigned short* cl = cand + i * CAP;
            for (int k2 = 0; k2 < nc; k2++) minIdx[cl[k2]] = 0x7FFFFFFFu;
        }
        if (tid == 0) nNext = 0;
        __syncthreads();
        for (int idx = tid; idx < na; idx += NTH) {
            int i = A[idx];
            int nc = candCnt[i];
            const unsigned short* cl = cand + i * CAP;
            for (int k2 = 0; k2 < nc; k2++)
                atomicMin(&minIdx[cl[k2]], (unsigned)i);
        }
        __syncthreads();
        for (int idx = tid; idx < na; idx += NTH) {
            int i = A[idx];
            int nc = candCnt[i];
            const unsigned short* cl = cand + i * CAP;
            bool ok = true;
            for (int k2 = 0; k2 < nc; k2++)
                if (minIdx[cl[k2]] < (unsigned)i) { ok = false; break; }
            if (ok) {
                for (int k2 = 0; k2 < nc; k2++) {
                    int j = cl[k2];
                    if (!((taken[j >> 5] >> (j & 31)) & 1u)) {
                        atomicOr(&taken[j >> 5], 1u << (j & 31));
                        tpF[ppos[i]] = 1;
                        mtF[tpos[j]] = 1;
                        break;
                    }
                }
            } else {
                int p = atomicAdd(&nNext, 1);
                Bn[p] = (unsigned short)i;
            }
        }
        __syncthreads();
        if (tid == 0) nact = nNext;
        parity ^= 1;
    }

    // ---- write tp/fp/fn ----
    const int tpB = OFF_TP + (b * 2 + e) * 4096;
    const int fpB = OFF_FP + (b * 2 + e) * 4096;
    const int fnB = OFF_FN + (b * 2 + e) * 4096;
    for (int q = 0; q < 4; q++) {
        int s = tid * 4 + q;
        int tp = tpF[s];
        int kp = (out[kpBase + s] > 0.5f) ? 1 : 0;
        int kt = (out[ktBase + s] > 0.5f) ? 1 : 0;
        out[tpB + s] = (float)tp;
        out[fpB + s] = (kp && !tp) ? 1.0f : 0.0f;
        out[fnB + s] = (kt && !mtF[s]) ? 1.0f : 0.0f;
    }
}

// ---------------------------------------------------------------------------
extern "C" void kernel_launch(void* const* d_in, const int* in_sizes, int n_in,
                              void* d_out, int out_size)
{
    const float* pred = (const float*)d_in[0];
    const float* targ = (const float*)d_in[1];
    float* out = (float*)d_out;

    cudaFuncSetAttribute(k_nms2, cudaFuncAttributeMaxDynamicSharedMemorySize, 168 * 1024);
    cudaFuncSetAttribute(k_match, cudaFuncAttributeMaxDynamicSharedMemorySize, 184 * 1024);

    k_sortA<<<64, NTH, 8 * 1024>>>(pred, targ);
    k_sortB<<<32, NTH, 16 * 1024>>>();
    k_coords<<<32, NTH, 32 * 1024>>>(pred, targ, out);
    k_nms2<<<16, NTH, 168 * 1024>>>(out);
    k_match<<<8, NTH, 184 * 1024>>>(out);
}

// round 14
// speedup vs baseline: 3.0207x; 1.2542x over previous
#include <cuda_runtime.h>
#include <cstdint>

#define NPTS 4096
#define NTH  1024

// d_out float32 layout:
//   Pc [4][2][4096][3] @0, Tc @98304, keepP @196608, keepT @229376,
//   tp @262144, fp @294912, fn @327680
#define OFF_TC 98304
#define OFF_KP 196608
#define OFF_KT 229376
#define OFF_TP 262144
#define OFF_FP 294912
#define OFF_FN 327680

#define NBX 32
#define NBZ 8
#define CAP 12
#define NNCAP 16
#define MAXV 2048

__device__ unsigned long long g_run0[16 * 4096];
__device__ unsigned long long g_run1[16 * 4096];
// per-half compacted valid points (sorted order preserved)
__device__ float g_vx[16 * 4096];
__device__ float g_vy[16 * 4096];
__device__ float g_vz[16 * 4096];
__device__ unsigned short g_vs[16 * 4096];
__device__ int g_vcnt[32];
// earlier-neighbor lists (built by k_build, consumed by k_resolve)
__device__ unsigned short g_nbr[16 * 2048 * NNCAP];
__device__ unsigned char g_nbrCnt[16 * 2048];
// NMS-kept compact lists per problem
__device__ float g_kx[16 * 2048];
__device__ float g_ky[16 * 2048];
__device__ float g_kz[16 * 2048];
__device__ unsigned short g_kpos[16 * 2048];
__device__ int g_kcnt[16];

__device__ __forceinline__ float dist2(float ax, float ay, float az,
                                       float bx, float by, float bz) {
    float dx = __fadd_rn(ax, -bx);
    float dy = __fadd_rn(ay, -by);
    float dz = __fadd_rn(az, -bz);
    return __fadd_rn(__fadd_rn(__fmul_rn(dx, dx), __fmul_rn(dy, dy)),
                     __fmul_rn(dz, dz));
}

__device__ __forceinline__ int clampi(int v, int lo, int hi) {
    return v < lo ? lo : (v > hi ? hi : v);
}

__device__ __forceinline__ void binCoords(float x, float y, float z,
                                          float invXY, float invZ,
                                          int& bx, int& by, int& bz) {
    bx = clampi((int)floorf(__fmul_rn(__fadd_rn(x, 4.5f), invXY)), 0, NBX - 1);
    by = clampi((int)floorf(__fmul_rn(__fadd_rn(y, 4.5f), invXY)), 0, NBX - 1);
    bz = clampi((int)floorf(__fmul_rn(__fadd_rn(z, 4.0f), invZ)),  0, NBZ - 1);
}

__device__ __forceinline__ int blockScanExcl(int cnt, int* wsum, int tid) {
    int lane = tid & 31, wid = tid >> 5;
    int v = cnt;
    for (int o = 1; o < 32; o <<= 1) {
        int nn = __shfl_up_sync(0xFFFFFFFFu, v, o);
        if (lane >= o) v += nn;
    }
    if (lane == 31) wsum[wid] = v;
    __syncthreads();
    if (wid == 0) {
        int w = wsum[lane];
        for (int o = 1; o < 32; o <<= 1) {
            int nn = __shfl_up_sync(0xFFFFFFFFu, w, o);
            if (lane >= o) w += nn;
        }
        wsum[lane] = w;
    }
    __syncthreads();
    return v - cnt + (wid ? wsum[wid - 1] : 0);
}

// ---------------------------------------------------------------------------
// Kernel A (64 blocks): sort 1024-key runs -> g_run0
// ---------------------------------------------------------------------------
__global__ void __launch_bounds__(1024) k_sortA(const float* __restrict__ pred,
                                                const float* __restrict__ targ)
{
    extern __shared__ unsigned char sm[];
    unsigned long long* s = (unsigned long long*)sm;   // [1024]
    const int tid = threadIdx.x;
    const int bi = blockIdx.x;
    const int prob = bi >> 2;
    const int quarter = bi & 3;
    const int t = prob >> 3;
    const int be = prob & 7;
    const int b = be >> 1;
    const int e = be & 1;
    const float* in = (t == 0) ? pred : targ;

    int n = quarter * 1024 + tid;
    int z = n >> 10, x = (n >> 5) & 31, y = n & 31;
    int base = ((((b * 32 + x) * 32 + y) * 4 + z) * 8) + e * 4;
    float conf = in[base + 3];
    unsigned u = __float_as_uint(conf);
    u = (u & 0x80000000u) ? ~u : (u | 0x80000000u);
    unsigned long long v = (((unsigned long long)(~u)) << 32) | (unsigned)n;

    for (int k = 2; k <= 1024; k <<= 1) {
        bool up = ((tid & k) == 0);
        for (int j = k >> 1; j > 0; j >>= 1) {
            unsigned long long p;
            if (j >= 32) {
                s[tid] = v;
                __syncthreads();
                p = s[tid ^ j];
                __syncthreads();
            } else {
                p = __shfl_xor_sync(0xFFFFFFFFu, v, j);
            }
            bool lower = ((tid & j) == 0);
            bool kmin = (lower == up);
            unsigned long long mn = v < p ? v : p;
            unsigned long long mx = v < p ? p : v;
            v = kmin ? mn : mx;
        }
    }
    g_run0[prob * 4096 + quarter * 1024 + tid] = v;
}

// ---------------------------------------------------------------------------
// Kernel B (32 blocks): merge 1024+1024 -> 2048 -> g_run1
// ---------------------------------------------------------------------------
__global__ void __launch_bounds__(1024) k_sortB()
{
    extern __shared__ unsigned char sm[];
    unsigned long long* sA = (unsigned long long*)sm;              // [1024]
    unsigned long long* sB = (unsigned long long*)(sm + 8 * 1024); // [1024]
    const int tid = threadIdx.x;
    const int prob = blockIdx.x >> 1;
    const int half = blockIdx.x & 1;
    const unsigned long long* src = g_run0 + prob * 4096 + half * 2048;
    sA[tid] = src[tid];
    sB[tid] = src[1024 + tid];
    __syncthreads();

    int diag = tid * 2;
    int lo = diag > 1024 ? diag - 1024 : 0;
    int hi = diag < 1024 ? diag : 1024;
    while (lo < hi) {
        int mid = (lo + hi) >> 1;
        if (sA[mid] < sB[diag - 1 - mid]) lo = mid + 1; else hi = mid;
    }
    int ai = lo, bj = diag - lo;
    unsigned long long* dst = g_run1 + prob * 4096 + half * 2048;
    #pragma unroll
    for (int r = 0; r < 2; r++) {
        bool takeA = (bj >= 1024) || (ai < 1024 && sA[ai] <= sB[bj]);
        dst[diag + r] = takeA ? sA[ai++] : sB[bj++];
    }
}

// ---------------------------------------------------------------------------
// Kernel C1 (32 blocks, 2/problem): merge-path half -> coords -> Pc/Tc
//   + per-half order-preserving valid compaction -> g_v*
// ---------------------------------------------------------------------------
__global__ void __launch_bounds__(1024) k_coords(const float* __restrict__ pred,
                                                 const float* __restrict__ targ,
                                                 float* __restrict__ out)
{
    extern __shared__ unsigned char sm[];
    unsigned long long* sA2 = (unsigned long long*)sm;             // [2048] 16KB
    unsigned long long* sB2 = (unsigned long long*)(sm + 16 * 1024);
    __shared__ int wsum[32];

    const int tid = threadIdx.x;
    const int bi = blockIdx.x;
    const int prob = bi >> 1;
    const int half = bi & 1;
    const int t = prob >> 3;
    const int be = prob & 7;
    const int b = be >> 1;
    const int e = be & 1;
    const float* in = (t == 0) ? pred : targ;

    {
        const unsigned long long* src = g_run1 + prob * 4096;
        sA2[tid] = src[tid];
        sA2[1024 + tid] = src[1024 + tid];
        sB2[tid] = src[2048 + tid];
        sB2[1024 + tid] = src[3072 + tid];
    }
    __syncthreads();

    const int diag = half * 2048 + tid * 2;
    int lo = diag > 2048 ? diag - 2048 : 0;
    int hi = diag < 2048 ? diag : 2048;
    while (lo < hi) {
        int mid = (lo + hi) >> 1;
        if (sA2[mid] < sB2[diag - 1 - mid]) lo = mid + 1; else hi = mid;
    }
    int ai = lo, bj = diag - lo;
    unsigned long long myk[2];
    #pragma unroll
    for (int r = 0; r < 2; r++) {
        bool takeA = (bj >= 2048) || (ai < 2048 && sA2[ai] <= sB2[bj]);
        myk[r] = takeA ? sA2[ai++] : sB2[bj++];
    }

    float rx[2], ry[2], rz[2];
    int vf[2]; int cnt = 0;
    #pragma unroll
    for (int q = 0; q < 2; q++) {
        int n = (int)(myk[q] & 0xFFFFFFFFull);
        int z = n >> 10, x = (n >> 5) & 31, y = n & 31;
        int base = ((((b * 32 + x) * 32 + y) * 4 + z) * 8) + e * 4;
        float4 vv = *(const float4*)(in + base);
        float c0 = __fmul_rn(__fadd_rn(vv.z, (float)z), 0.75f);
        float c1 = __fmul_rn(__fadd_rn(vv.x, (float)x), 0.78125f);
        float c2 = __fmul_rn(__fadd_rn(vv.y, (float)y), 0.78125f);
        rx[q] = c0; ry[q] = c1; rz[q] = c2;
        vf[q] = (vv.w > 0.5f) ? 1 : 0;
        cnt += vf[q];
        int s = diag + q;
        int ob = (t ? OFF_TC : 0) + ((b * 2 + e) * 4096 + s) * 3;
        out[ob + 0] = c0; out[ob + 1] = c1; out[ob + 2] = c2;
    }

    int excl = blockScanExcl(cnt, wsum, tid);
    int gb = prob * 4096 + half * 2048;
    #pragma unroll
    for (int q = 0; q < 2; q++) {
        if (vf[q]) {
            g_vx[gb + excl] = rx[q];
            g_vy[gb + excl] = ry[q];
            g_vz[gb + excl] = rz[q];
            g_vs[gb + excl] = (unsigned short)(diag + q);
            excl++;
        }
    }
    if (tid == 0) g_vcnt[bi] = wsum[31];
}

// ---------------------------------------------------------------------------
// Kernel C2a (64 blocks, 4/problem): stitch -> bins -> neighbor lists for
//   one quarter of the points -> g_nbr / g_nbrCnt
// ---------------------------------------------------------------------------
__global__ void __launch_bounds__(1024) k_build()
{
    extern __shared__ unsigned char sm[];
    float* cx = (float*)sm;                                      // 8KB
    float* cy = (float*)(sm + 8 * 1024);
    float* cz = (float*)(sm + 16 * 1024);
    unsigned int* binCnt = (unsigned int*)(sm + 24 * 1024);      // 32KB
    unsigned int* binStart = (unsigned int*)(sm + 56 * 1024);    // 32KB
    unsigned short* binPts = (unsigned short*)(sm + 88 * 1024);  // 4KB

    __shared__ int wsum[32];

    const int tid = threadIdx.x;
    const int bi = blockIdx.x;
    const int prob = bi >> 2;
    const int quarter = bi & 3;
    const int e = prob & 1;
    const float de = (e == 0) ? (float)(0.74 * 1.4) : (float)(0.528 * 1.4);
    const float dd = __fmul_rn(de, de);
    const float cellXY = fmaxf(de, 1.02f);
    const float invXY = 1.0f / cellXY;
    const float invZ = 1.0f / 1.3125f;

    const int c0 = min(g_vcnt[prob * 2], MAXV);
    const int c1 = g_vcnt[prob * 2 + 1];
    const int m = min(c0 + c1, MAXV);
    const int gb = prob * 4096;

    // stitch halves (order-preserving)
    for (int i = tid; i < c0; i += NTH) {
        cx[i] = g_vx[gb + i]; cy[i] = g_vy[gb + i]; cz[i] = g_vz[gb + i];
    }
    for (int i = tid; i < m - c0; i += NTH) {
        cx[c0 + i] = g_vx[gb + 2048 + i];
        cy[c0 + i] = g_vy[gb + 2048 + i];
        cz[c0 + i] = g_vz[gb + 2048 + i];
    }
    for (int i = tid; i < NBX * NBX * NBZ; i += NTH) binCnt[i] = 0;
    __syncthreads();

    // ---- bins over all m points ----
    for (int ci = tid; ci < m; ci += NTH) {
        int bx, by, bz;
        binCoords(cx[ci], cy[ci], cz[ci], invXY, invZ, bx, by, bz);
        atomicAdd(&binCnt[(bz * NBX + by) * NBX + bx], 1u);
    }
    __syncthreads();
    {
        int base8 = tid * 8;
        int loc[8]; int s = 0;
        for (int k2 = 0; k2 < 8; k2++) { loc[k2] = s; s += (int)binCnt[base8 + k2]; }
        int ex = blockScanExcl(s, wsum, tid);
        for (int k2 = 0; k2 < 8; k2++) binStart[base8 + k2] = (unsigned)(ex + loc[k2]);
    }
    __syncthreads();
    for (int i = tid; i < NBX * NBX * NBZ; i += NTH) binCnt[i] = 0;
    __syncthreads();
    for (int ci = tid; ci < m; ci += NTH) {
        int bx, by, bz;
        binCoords(cx[ci], cy[ci], cz[ci], invXY, invZ, bx, by, bz);
        int bb = (bz * NBX + by) * NBX + bx;
        unsigned off = atomicAdd(&binCnt[bb], 1u);
        binPts[binStart[bb] + off] = (unsigned short)ci;
    }
    __syncthreads();

    // ---- neighbor lists for our quarter of points (x-range scan) ----
    const int seg = (m + 3) >> 2;
    const int st0 = quarter * seg;
    const int en0 = min(st0 + seg, m);
    for (int ci = st0 + tid; ci < en0; ci += NTH) {
        float px = cx[ci], py = cy[ci], pz = cz[ci];
        int bx, by, bz;
        binCoords(px, py, pz, invXY, invZ, bx, by, bz);
        int x0 = bx > 0 ? bx - 1 : 0;
        int x1 = bx < NBX - 1 ? bx + 1 : NBX - 1;
        int nc = 0;
        unsigned short loc[NNCAP];
        #pragma unroll
        for (int dzb = -1; dzb <= 1; dzb++) {
            int Z = bz + dzb;
            if (Z < 0 || Z >= NBZ) continue;
            #pragma unroll
            for (int dyb = -1; dyb <= 1; dyb++) {
                int Y = by + dyb;
                if (Y < 0 || Y >= NBX) continue;
                int row = (Z * NBX + Y) * NBX;
                unsigned st = binStart[row + x0];
                unsigned en = binStart[row + x1] + binCnt[row + x1];
                for (unsigned p = st; p < en; p++) {
                    int a = binPts[p];
                    if (a < ci) {
                        float d2 = dist2(px, py, pz, cx[a], cy[a], cz[a]);
                        if (d2 < dd && nc < NNCAP)
                            loc[nc++] = (unsigned short)a;
                    }
                }
            }
        }
        g_nbrCnt[prob * 2048 + ci] = (unsigned char)nc;
        unsigned short* dst = g_nbr + (prob * 2048 + ci) * NNCAP;
        for (int k2 = 0; k2 < nc; k2++) dst[k2] = loc[k2];
    }
}

// ---------------------------------------------------------------------------
// Kernel C2b (16 blocks): load lists -> barrier-free wave NMS -> keep masks
//   + kept compact lists -> g_k*
// ---------------------------------------------------------------------------
__global__ void __launch_bounds__(1024) k_resolve(float* __restrict__ out)
{
    extern __shared__ unsigned char sm[];
    float* cx = (float*)sm;                                      // 8KB
    float* cy = (float*)(sm + 8 * 1024);
    float* cz = (float*)(sm + 16 * 1024);
    unsigned short* spos = (unsigned short*)(sm + 24 * 1024);    // 4KB
    unsigned char* fullk = (unsigned char*)(sm + 28 * 1024);     // 4KB
    unsigned short* nbr = (unsigned short*)(sm + 32 * 1024);     // 64KB
    unsigned char* nbrCnt = (unsigned char*)(sm + 96 * 1024);    // 2KB
    unsigned char* state = (unsigned char*)(sm + 98 * 1024);     // 2KB

    __shared__ int wsum[32];

    const int tid = threadIdx.x;
    const int prob = blockIdx.x;
    const int t = prob >> 3;
    const int be = prob & 7;
    const int b = be >> 1;
    const int e = be & 1;

    const int c0 = min(g_vcnt[prob * 2], MAXV);
    const int c1 = g_vcnt[prob * 2 + 1];
    const int m = min(c0 + c1, MAXV);
    const int gb = prob * 4096;

    // stitch halves (coords + spos)
    for (int i = tid; i < c0; i += NTH) {
        cx[i] = g_vx[gb + i]; cy[i] = g_vy[gb + i]; cz[i] = g_vz[gb + i];
        spos[i] = g_vs[gb + i];
    }
    for (int i = tid; i < m - c0; i += NTH) {
        cx[c0 + i] = g_vx[gb + 2048 + i];
        cy[c0 + i] = g_vy[gb + 2048 + i];
        cz[c0 + i] = g_vz[gb + 2048 + i];
        spos[c0 + i] = g_vs[gb + 2048 + i];
    }
    // coalesced u32 copy of neighbor lists (stale tails unused)
    {
        const unsigned int* src = (const unsigned int*)(g_nbr + prob * 2048 * NNCAP);
        unsigned int* dst = (unsigned int*)nbr;
        int words = m * (NNCAP / 2);
        for (int i = tid; i < words; i += NTH) dst[i] = src[i];
    }
    for (int i = tid; i < m; i += NTH) {
        unsigned char nc = g_nbrCnt[prob * 2048 + i];
        nbrCnt[i] = nc;
        state[i] = (nc == 0) ? (unsigned char)1 : (unsigned char)0;
    }
    for (int q = 0; q < 4; q++) fullk[tid * 4 + q] = 0;
    __syncthreads();

    // ---- barrier-free wave NMS fixpoint (confluent, monotone) ----
    {
        volatile unsigned char* vst = (volatile unsigned char*)state;
        int p0 = tid, p1 = tid + NTH;
        bool d0 = (p0 >= m) || (state[p0] != 0);
        bool d1 = (p1 >= m) || (state[p1] != 0);
        while (!(d0 && d1)) {
            if (!d0) {
                int nc = nbrCnt[p0];
                const unsigned short* nl = nbr + p0 * NNCAP;
                bool anyK = false, allS = true;
                for (int k2 = 0; k2 < nc; k2++) {
                    unsigned char s2 = vst[nl[k2]];
                    if (s2 == 1) { anyK = true; break; }
                    allS &= (s2 == 2);
                }
                if (anyK) { vst[p0] = 2; d0 = true; }
                else if (allS) { vst[p0] = 1; d0 = true; }
            }
            if (!d1) {
                int nc = nbrCnt[p1];
                const unsigned short* nl = nbr + p1 * NNCAP;
                bool anyK = false, allS = true;
                for (int k2 = 0; k2 < nc; k2++) {
                    unsigned char s2 = vst[nl[k2]];
                    if (s2 == 1) { anyK = true; break; }
                    allS &= (s2 == 2);
                }
                if (anyK) { vst[p1] = 2; d1 = true; }
                else if (allS) { vst[p1] = 1; d1 = true; }
            }
        }
    }
    __syncthreads();

    // ---- keep mask scatter ----
    for (int ci = tid; ci < m; ci += NTH)
        fullk[spos[ci]] = (state[ci] == 1) ? 1 : 0;

    // ---- order-preserving compaction of kept -> g_k* ----
    {
        int base2 = tid * 2;
        int k0 = (base2 < m) ? (state[base2] == 1) : 0;
        int k1 = (base2 + 1 < m) ? (state[base2 + 1] == 1) : 0;
        int ex2 = blockScanExcl(k0 + k1, wsum, tid);
        int kc = wsum[31];
        int kb2 = prob * 2048;
        if (k0) {
            g_kx[kb2 + ex2] = cx[base2]; g_ky[kb2 + ex2] = cy[base2];
            g_kz[kb2 + ex2] = cz[base2]; g_kpos[kb2 + ex2] = spos[base2];
            ex2++;
        }
        if (k1) {
            g_kx[kb2 + ex2] = cx[base2 + 1]; g_ky[kb2 + ex2] = cy[base2 + 1];
            g_kz[kb2 + ex2] = cz[base2 + 1]; g_kpos[kb2 + ex2] = spos[base2 + 1];
        }
        if (tid == 0) g_kcnt[prob] = kc;
    }

    // ---- write keep mask ----
    int kb = (t ? OFF_KT : OFF_KP) + (b * 2 + e) * 4096;
    for (int q = 0; q < 4; q++) {
        int s = tid * 4 + q;
        out[kb + s] = (float)fullk[s];
    }
}

// ---------------------------------------------------------------------------
// Kernel D (8 blocks): matching; candidate build uses x-range scan
// ---------------------------------------------------------------------------
__global__ void __launch_bounds__(1024) k_match(float* __restrict__ out)
{
    extern __shared__ unsigned char sm[];
    float* cpx = (float*)sm;
    float* cpy = (float*)(sm + 8 * 1024);
    float* cpz = (float*)(sm + 16 * 1024);
    float* ctx = (float*)(sm + 24 * 1024);
    float* cty = (float*)(sm + 32 * 1024);
    float* ctz = (float*)(sm + 40 * 1024);
    unsigned short* ppos = (unsigned short*)(sm + 48 * 1024);
    unsigned short* tpos = (unsigned short*)(sm + 52 * 1024);
    unsigned int* binCnt = (unsigned int*)(sm + 56 * 1024);
    unsigned int* binStart = (unsigned int*)(sm + 88 * 1024);
    unsigned short* binPts = (unsigned short*)(sm + 120 * 1024);
    unsigned char* candCnt = (unsigned char*)(sm + 124 * 1024);
    unsigned short* cand = (unsigned short*)(sm + 126 * 1024);
    unsigned char* tpF = (unsigned char*)(sm + 174 * 1024);
    unsigned char* mtF = (unsigned char*)(sm + 178 * 1024);
    unsigned int* taken = (unsigned int*)(sm + 182 * 1024);
    unsigned int* minIdx = (unsigned int*)(sm + 56 * 1024);    // alias binCnt
    unsigned short* actA = (unsigned short*)(sm + 88 * 1024);  // alias binStart
    unsigned short* actB = (unsigned short*)(sm + 92 * 1024);

    __shared__ int wsum[32];
    __shared__ int nact, nNext;

    const int tid = threadIdx.x;
    const int be = blockIdx.x;
    const int b = be >> 1, e = be & 1;
    const float de = (e == 0) ? (float)(0.74 * 1.4) : (float)(0.528 * 1.4);
    const float dd = __fmul_rn(de, de);
    const float cellXY = fmaxf(de, 1.02f);
    const float invXY = 1.0f / cellXY;
    const float invZ = 1.0f / 1.3125f;

    const int kpBase = OFF_KP + (b * 2 + e) * 4096;
    const int ktBase = OFF_KT + (b * 2 + e) * 4096;
    const int pP = be, pT = 8 + be;

    const int KP = min(g_kcnt[pP], 2048);
    const int KT = min(g_kcnt[pT], 2048);

    for (int i = tid; i < KP; i += NTH) {
        cpx[i] = g_kx[pP * 2048 + i];
        cpy[i] = g_ky[pP * 2048 + i];
        cpz[i] = g_kz[pP * 2048 + i];
        ppos[i] = g_kpos[pP * 2048 + i];
    }
    for (int i = tid; i < KT; i += NTH) {
        ctx[i] = g_kx[pT * 2048 + i];
        cty[i] = g_ky[pT * 2048 + i];
        ctz[i] = g_kz[pT * 2048 + i];
        tpos[i] = g_kpos[pT * 2048 + i];
    }
    for (int i = tid; i < NBX * NBX * NBZ; i += NTH) binCnt[i] = 0;
    if (tid < 64) taken[tid] = 0u;
    if (tid == 0) { nact = 0; nNext = 0; }
    for (int q = 0; q < 4; q++) { tpF[tid * 4 + q] = 0; mtF[tid * 4 + q] = 0; }
    __syncthreads();

    // ---- bin kept targets ----
    for (int ci = tid; ci < KT; ci += NTH) {
        int bx, by, bz;
        binCoords(ctx[ci], cty[ci], ctz[ci], invXY, invZ, bx, by, bz);
        atomicAdd(&binCnt[(bz * NBX + by) * NBX + bx], 1u);
    }
    __syncthreads();
    {
        int base8 = tid * 8;
        int loc[8]; int s = 0;
        for (int k2 = 0; k2 < 8; k2++) { loc[k2] = s; s += (int)binCnt[base8 + k2]; }
        int ex = blockScanExcl(s, wsum, tid);
        for (int k2 = 0; k2 < 8; k2++) binStart[base8 + k2] = (unsigned)(ex + loc[k2]);
    }
    __syncthreads();
    for (int i = tid; i < NBX * NBX * NBZ; i += NTH) binCnt[i] = 0;
    __syncthreads();
    for (int ci = tid; ci < KT; ci += NTH) {
        int bx, by, bz;
        binCoords(ctx[ci], cty[ci], ctz[ci], invXY, invZ, bx, by, bz);
        int bb = (bz * NBX + by) * NBX + bx;
        unsigned off = atomicAdd(&binCnt[bb], 1u);
        binPts[binStart[bb] + off] = (unsigned short)ci;
    }
    __syncthreads();

    // ---- per-pred sorted candidate lists (contiguous x-range scan) ----
    for (int ci = tid; ci < KP; ci += NTH) {
        float px = cpx[ci], py = cpy[ci], pz = cpz[ci];
        int bx, by, bz;
        binCoords(px, py, pz, invXY, invZ, bx, by, bz);
        int x0 = bx > 0 ? bx - 1 : 0;
        int x1 = bx < NBX - 1 ? bx + 1 : NBX - 1;
        unsigned short* cl = cand + ci * CAP;
        int nc = 0;
        #pragma unroll
        for (int dzb = -1; dzb <= 1; dzb++) {
            int Z = bz + dzb;
            if (Z < 0 || Z >= NBZ) continue;
            #pragma unroll
            for (int dyb = -1; dyb <= 1; dyb++) {
                int Y = by + dyb;
                if (Y < 0 || Y >= NBX) continue;
                int row = (Z * NBX + Y) * NBX;
                unsigned st = binStart[row + x0];
                unsigned en = binStart[row + x1] + binCnt[row + x1];
                for (unsigned p = st; p < en; p++) {
                    int a = binPts[p];
                    float d2 = dist2(px, py, pz, ctx[a], cty[a], ctz[a]);
                    if (d2 < dd) {
                        if (nc < CAP) {
                            int k2 = nc;
                            while (k2 > 0 && cl[k2 - 1] > a) { cl[k2] = cl[k2 - 1]; k2--; }
                            cl[k2] = (unsigned short)a;
                            nc++;
                        } else if (a < cl[CAP - 1]) {
                            int k2 = CAP - 1;
                            while (k2 > 0 && cl[k2 - 1] > a) { cl[k2] = cl[k2 - 1]; k2--; }
                            cl[k2] = (unsigned short)a;
                        }
                    }
                }
            }
        }
        candCnt[ci] = (unsigned char)nc;
    }
    __syncthreads();     // bins dead; actA/actB alias binStart region

    // ---- initial active list ----
    for (int i = tid; i < KP; i += NTH) {
        if (candCnt[i] > 0) {
            int p = atomicAdd(&nact, 1);
            actA[p] = (unsigned short)i;
        }
    }
    int parity = 0;

    // ---- active-list wave resolution (exact sequential semantics) ----
    while (true) {
        __syncthreads();
        int na = nact;
        if (na <= 0) break;
        const unsigned short* A = parity ? actB : actA;
        unsigned short* Bn = parity ? actA : actB;

        for (int idx = tid; idx < na; idx += NTH) {
            int i = A[idx];
            int nc = candCnt[i];
            const unsigned short* cl = cand + i * CAP;
            for (int k2 = 0; k2 < nc; k2++) minIdx[cl[k2]] = 0x7FFFFFFFu;
        }
        if (tid == 0) nNext = 0;
        __syncthreads();
        for (int idx = tid; idx < na; idx += NTH) {
            int i = A[idx];
            int nc = candCnt[i];
            const unsigned short* cl = cand + i * CAP;
            for (int k2 = 0; k2 < nc; k2++)
                atomicMin(&minIdx[cl[k2]], (unsigned)i);
        }
        __syncthreads();
        for (int idx = tid; idx < na; idx += NTH) {
            int i = A[idx];
            int nc = candCnt[i];
            const unsigned short* cl = cand + i * CAP;
            bool ok = true;
            for (int k2 = 0; k2 < nc; k2++)
                if (minIdx[cl[k2]] < (unsigned)i) { ok = false; break; }
            if (ok) {
                for (int k2 = 0; k2 < nc; k2++) {
                    int j = cl[k2];
                    if (!((taken[j >> 5] >> (j & 31)) & 1u)) {
                        atomicOr(&taken[j >> 5], 1u << (j & 31));
                        tpF[ppos[i]] = 1;
                        mtF[tpos[j]] = 1;
                        break;
                    }
                }
            } else {
                int p = atomicAdd(&nNext, 1);
                Bn[p] = (unsigned short)i;
            }
        }
        __syncthreads();
        if (tid == 0) nact = nNext;
        parity ^= 1;
    }

    // ---- write tp/fp/fn ----
    const int tpB = OFF_TP + (b * 2 + e) * 4096;
    const int fpB = OFF_FP + (b * 2 + e) * 4096;
    const int fnB = OFF_FN + (b * 2 + e) * 4096;
    for (int q = 0; q < 4; q++) {
        int s = tid * 4 + q;
        int tp = tpF[s];
        int kp = (out[kpBase + s] > 0.5f) ? 1 : 0;
        int kt = (out[ktBase + s] > 0.5f) ? 1 : 0;
        out[tpB + s] = (float)tp;
        out[fpB + s] = (kp && !tp) ? 1.0f : 0.0f;
        out[fnB + s] = (kt && !mtF[s]) ? 1.0f : 0.0f;
    }
}

// ---------------------------------------------------------------------------
extern "C" void kernel_launch(void* const* d_in, const int* in_sizes, int n_in,
                              void* d_out, int out_size)
{
    const float* pred = (const float*)d_in[0];
    const float* targ = (const float*)d_in[1];
    float* out = (float*)d_out;

    cudaFuncSetAttribute(k_build, cudaFuncAttributeMaxDynamicSharedMemorySize, 96 * 1024);
    cudaFuncSetAttribute(k_resolve, cudaFuncAttributeMaxDynamicSharedMemorySize, 104 * 1024);
    cudaFuncSetAttribute(k_match, cudaFuncAttributeMaxDynamicSharedMemorySize, 184 * 1024);

    k_sortA<<<64, NTH, 8 * 1024>>>(pred, targ);
    k_sortB<<<32, NTH, 16 * 1024>>>();
    k_coords<<<32, NTH, 32 * 1024>>>(pred, targ, out);
    k_build<<<64, NTH, 92 * 1024>>>();
    k_resolve<<<16, NTH, 104 * 1024>>>(out);
    k_match<<<8, NTH, 184 * 1024>>>(out);
}

// round 15
// speedup vs baseline: 3.0398x; 1.0063x over previous
#include <cuda_runtime.h>
#include <cstdint>

#define NPTS 4096
#define NTH  1024

// d_out float32 layout:
//   Pc [4][2][4096][3] @0, Tc @98304, keepP @196608, keepT @229376,
//   tp @262144, fp @294912, fn @327680
#define OFF_TC 98304
#define OFF_KP 196608
#define OFF_KT 229376
#define OFF_TP 262144
#define OFF_FP 294912
#define OFF_FN 327680

#define NBX 32
#define NBZ 8
#define CAP 12
#define NNCAP 16
#define MAXV 2048

__device__ unsigned long long g_run0[16 * 4096];
__device__ unsigned long long g_run1[16 * 4096];
// per-half compacted valid points (sorted order preserved)
__device__ float g_vx[16 * 4096];
__device__ float g_vy[16 * 4096];
__device__ float g_vz[16 * 4096];
__device__ unsigned short g_vs[16 * 4096];
__device__ int g_vcnt[32];
// earlier-neighbor lists (NMS)
__device__ unsigned short g_nbr[16 * 2048 * NNCAP];
__device__ unsigned char g_nbrCnt[16 * 2048];
// NMS-kept compact lists per problem
__device__ float g_kx[16 * 2048];
__device__ float g_ky[16 * 2048];
__device__ float g_kz[16 * 2048];
__device__ unsigned short g_kpos[16 * 2048];
__device__ int g_kcnt[16];
// matching candidate lists (built by k_mbuild, consumed by k_mresolve)
__device__ unsigned short g_cand[8 * 2048 * CAP];
__device__ unsigned char g_candCnt[8 * 2048];

__device__ __forceinline__ float dist2(float ax, float ay, float az,
                                       float bx, float by, float bz) {
    float dx = __fadd_rn(ax, -bx);
    float dy = __fadd_rn(ay, -by);
    float dz = __fadd_rn(az, -bz);
    return __fadd_rn(__fadd_rn(__fmul_rn(dx, dx), __fmul_rn(dy, dy)),
                     __fmul_rn(dz, dz));
}

__device__ __forceinline__ int clampi(int v, int lo, int hi) {
    return v < lo ? lo : (v > hi ? hi : v);
}

__device__ __forceinline__ void binCoords(float x, float y, float z,
                                          float invXY, float invZ,
                                          int& bx, int& by, int& bz) {
    bx = clampi((int)floorf(__fmul_rn(__fadd_rn(x, 4.5f), invXY)), 0, NBX - 1);
    by = clampi((int)floorf(__fmul_rn(__fadd_rn(y, 4.5f), invXY)), 0, NBX - 1);
    bz = clampi((int)floorf(__fmul_rn(__fadd_rn(z, 4.0f), invZ)),  0, NBZ - 1);
}

__device__ __forceinline__ int blockScanExcl(int cnt, int* wsum, int tid) {
    int lane = tid & 31, wid = tid >> 5;
    int v = cnt;
    for (int o = 1; o < 32; o <<= 1) {
        int nn = __shfl_up_sync(0xFFFFFFFFu, v, o);
        if (lane >= o) v += nn;
    }
    if (lane == 31) wsum[wid] = v;
    __syncthreads();
    if (wid == 0) {
        int w = wsum[lane];
        for (int o = 1; o < 32; o <<= 1) {
            int nn = __shfl_up_sync(0xFFFFFFFFu, w, o);
            if (lane >= o) w += nn;
        }
        wsum[lane] = w;
    }
    __syncthreads();
    return v - cnt + (wid ? wsum[wid - 1] : 0);
}

// ---------------------------------------------------------------------------
// Kernel A (64 blocks): sort 1024-key runs -> g_run0
// ---------------------------------------------------------------------------
__global__ void __launch_bounds__(1024) k_sortA(const float* __restrict__ pred,
                                                const float* __restrict__ targ)
{
    extern __shared__ unsigned char sm[];
    unsigned long long* s = (unsigned long long*)sm;   // [1024]
    const int tid = threadIdx.x;
    const int bi = blockIdx.x;
    const int prob = bi >> 2;
    const int quarter = bi & 3;
    const int t = prob >> 3;
    const int be = prob & 7;
    const int b = be >> 1;
    const int e = be & 1;
    const float* in = (t == 0) ? pred : targ;

    int n = quarter * 1024 + tid;
    int z = n >> 10, x = (n >> 5) & 31, y = n & 31;
    int base = ((((b * 32 + x) * 32 + y) * 4 + z) * 8) + e * 4;
    float conf = in[base + 3];
    unsigned u = __float_as_uint(conf);
    u = (u & 0x80000000u) ? ~u : (u | 0x80000000u);
    unsigned long long v = (((unsigned long long)(~u)) << 32) | (unsigned)n;

    for (int k = 2; k <= 1024; k <<= 1) {
        bool up = ((tid & k) == 0);
        for (int j = k >> 1; j > 0; j >>= 1) {
            unsigned long long p;
            if (j >= 32) {
                s[tid] = v;
                __syncthreads();
                p = s[tid ^ j];
                __syncthreads();
            } else {
                p = __shfl_xor_sync(0xFFFFFFFFu, v, j);
            }
            bool lower = ((tid & j) == 0);
            bool kmin = (lower == up);
            unsigned long long mn = v < p ? v : p;
            unsigned long long mx = v < p ? p : v;
            v = kmin ? mn : mx;
        }
    }
    g_run0[prob * 4096 + quarter * 1024 + tid] = v;
}

// ---------------------------------------------------------------------------
// Kernel B (32 blocks): merge 1024+1024 -> 2048 -> g_run1
// ---------------------------------------------------------------------------
__global__ void __launch_bounds__(1024) k_sortB()
{
    extern __shared__ unsigned char sm[];
    unsigned long long* sA = (unsigned long long*)sm;              // [1024]
    unsigned long long* sB = (unsigned long long*)(sm + 8 * 1024); // [1024]
    const int tid = threadIdx.x;
    const int prob = blockIdx.x >> 1;
    const int half = blockIdx.x & 1;
    const unsigned long long* src = g_run0 + prob * 4096 + half * 2048;
    sA[tid] = src[tid];
    sB[tid] = src[1024 + tid];
    __syncthreads();

    int diag = tid * 2;
    int lo = diag > 1024 ? diag - 1024 : 0;
    int hi = diag < 1024 ? diag : 1024;
    while (lo < hi) {
        int mid = (lo + hi) >> 1;
        if (sA[mid] < sB[diag - 1 - mid]) lo = mid + 1; else hi = mid;
    }
    int ai = lo, bj = diag - lo;
    unsigned long long* dst = g_run1 + prob * 4096 + half * 2048;
    #pragma unroll
    for (int r = 0; r < 2; r++) {
        bool takeA = (bj >= 1024) || (ai < 1024 && sA[ai] <= sB[bj]);
        dst[diag + r] = takeA ? sA[ai++] : sB[bj++];
    }
}

// ---------------------------------------------------------------------------
// Kernel C1 (32 blocks, 2/problem): merge-path half -> coords -> Pc/Tc
// ---------------------------------------------------------------------------
__global__ void __launch_bounds__(1024) k_coords(const float* __restrict__ pred,
                                                 const float* __restrict__ targ,
                                                 float* __restrict__ out)
{
    extern __shared__ unsigned char sm[];
    unsigned long long* sA2 = (unsigned long long*)sm;             // [2048] 16KB
    unsigned long long* sB2 = (unsigned long long*)(sm + 16 * 1024);
    __shared__ int wsum[32];

    const int tid = threadIdx.x;
    const int bi = blockIdx.x;
    const int prob = bi >> 1;
    const int half = bi & 1;
    const int t = prob >> 3;
    const int be = prob & 7;
    const int b = be >> 1;
    const int e = be & 1;
    const float* in = (t == 0) ? pred : targ;

    {
        const unsigned long long* src = g_run1 + prob * 4096;
        sA2[tid] = src[tid];
        sA2[1024 + tid] = src[1024 + tid];
        sB2[tid] = src[2048 + tid];
        sB2[1024 + tid] = src[3072 + tid];
    }
    __syncthreads();

    const int diag = half * 2048 + tid * 2;
    int lo = diag > 2048 ? diag - 2048 : 0;
    int hi = diag < 2048 ? diag : 2048;
    while (lo < hi) {
        int mid = (lo + hi) >> 1;
        if (sA2[mid] < sB2[diag - 1 - mid]) lo = mid + 1; else hi = mid;
    }
    int ai = lo, bj = diag - lo;
    unsigned long long myk[2];
    #pragma unroll
    for (int r = 0; r < 2; r++) {
        bool takeA = (bj >= 2048) || (ai < 2048 && sA2[ai] <= sB2[bj]);
        myk[r] = takeA ? sA2[ai++] : sB2[bj++];
    }

    float rx[2], ry[2], rz[2];
    int vf[2]; int cnt = 0;
    #pragma unroll
    for (int q = 0; q < 2; q++) {
        int n = (int)(myk[q] & 0xFFFFFFFFull);
        int z = n >> 10, x = (n >> 5) & 31, y = n & 31;
        int base = ((((b * 32 + x) * 32 + y) * 4 + z) * 8) + e * 4;
        float4 vv = *(const float4*)(in + base);
        float c0 = __fmul_rn(__fadd_rn(vv.z, (float)z), 0.75f);
        float c1 = __fmul_rn(__fadd_rn(vv.x, (float)x), 0.78125f);
        float c2 = __fmul_rn(__fadd_rn(vv.y, (float)y), 0.78125f);
        rx[q] = c0; ry[q] = c1; rz[q] = c2;
        vf[q] = (vv.w > 0.5f) ? 1 : 0;
        cnt += vf[q];
        int s = diag + q;
        int ob = (t ? OFF_TC : 0) + ((b * 2 + e) * 4096 + s) * 3;
        out[ob + 0] = c0; out[ob + 1] = c1; out[ob + 2] = c2;
    }

    int excl = blockScanExcl(cnt, wsum, tid);
    int gb = prob * 4096 + half * 2048;
    #pragma unroll
    for (int q = 0; q < 2; q++) {
        if (vf[q]) {
            g_vx[gb + excl] = rx[q];
            g_vy[gb + excl] = ry[q];
            g_vz[gb + excl] = rz[q];
            g_vs[gb + excl] = (unsigned short)(diag + q);
            excl++;
        }
    }
    if (tid == 0) g_vcnt[bi] = wsum[31];
}

// ---------------------------------------------------------------------------
// Kernel C2a (64 blocks, 4/problem): stitch -> bins -> neighbor lists for
//   one quarter of the points -> g_nbr / g_nbrCnt
// ---------------------------------------------------------------------------
__global__ void __launch_bounds__(1024) k_build()
{
    extern __shared__ unsigned char sm[];
    float* cx = (float*)sm;                                      // 8KB
    float* cy = (float*)(sm + 8 * 1024);
    float* cz = (float*)(sm + 16 * 1024);
    unsigned int* binCnt = (unsigned int*)(sm + 24 * 1024);      // 32KB
    unsigned int* binStart = (unsigned int*)(sm + 56 * 1024);    // 32KB
    unsigned short* binPts = (unsigned short*)(sm + 88 * 1024);  // 4KB

    __shared__ int wsum[32];

    const int tid = threadIdx.x;
    const int bi = blockIdx.x;
    const int prob = bi >> 2;
    const int quarter = bi & 3;
    const int e = prob & 1;
    const float de = (e == 0) ? (float)(0.74 * 1.4) : (float)(0.528 * 1.4);
    const float dd = __fmul_rn(de, de);
    const float cellXY = fmaxf(de, 1.02f);
    const float invXY = 1.0f / cellXY;
    const float invZ = 1.0f / 1.3125f;

    const int c0 = min(g_vcnt[prob * 2], MAXV);
    const int c1 = g_vcnt[prob * 2 + 1];
    const int m = min(c0 + c1, MAXV);
    const int gb = prob * 4096;

    for (int i = tid; i < c0; i += NTH) {
        cx[i] = g_vx[gb + i]; cy[i] = g_vy[gb + i]; cz[i] = g_vz[gb + i];
    }
    for (int i = tid; i < m - c0; i += NTH) {
        cx[c0 + i] = g_vx[gb + 2048 + i];
        cy[c0 + i] = g_vy[gb + 2048 + i];
        cz[c0 + i] = g_vz[gb + 2048 + i];
    }
    for (int i = tid; i < NBX * NBX * NBZ; i += NTH) binCnt[i] = 0;
    __syncthreads();

    for (int ci = tid; ci < m; ci += NTH) {
        int bx, by, bz;
        binCoords(cx[ci], cy[ci], cz[ci], invXY, invZ, bx, by, bz);
        atomicAdd(&binCnt[(bz * NBX + by) * NBX + bx], 1u);
    }
    __syncthreads();
    {
        int base8 = tid * 8;
        int loc[8]; int s = 0;
        for (int k2 = 0; k2 < 8; k2++) { loc[k2] = s; s += (int)binCnt[base8 + k2]; }
        int ex = blockScanExcl(s, wsum, tid);
        for (int k2 = 0; k2 < 8; k2++) binStart[base8 + k2] = (unsigned)(ex + loc[k2]);
    }
    __syncthreads();
    for (int i = tid; i < NBX * NBX * NBZ; i += NTH) binCnt[i] = 0;
    __syncthreads();
    for (int ci = tid; ci < m; ci += NTH) {
        int bx, by, bz;
        binCoords(cx[ci], cy[ci], cz[ci], invXY, invZ, bx, by, bz);
        int bb = (bz * NBX + by) * NBX + bx;
        unsigned off = atomicAdd(&binCnt[bb], 1u);
        binPts[binStart[bb] + off] = (unsigned short)ci;
    }
    __syncthreads();

    const int seg = (m + 3) >> 2;
    const int st0 = quarter * seg;
    const int en0 = min(st0 + seg, m);
    for (int ci = st0 + tid; ci < en0; ci += NTH) {
        float px = cx[ci], py = cy[ci], pz = cz[ci];
        int bx, by, bz;
        binCoords(px, py, pz, invXY, invZ, bx, by, bz);
        int x0 = bx > 0 ? bx - 1 : 0;
        int x1 = bx < NBX - 1 ? bx + 1 : NBX - 1;
        int nc = 0;
        unsigned short loc[NNCAP];
        #pragma unroll
        for (int dzb = -1; dzb <= 1; dzb++) {
            int Z = bz + dzb;
            if (Z < 0 || Z >= NBZ) continue;
            #pragma unroll
            for (int dyb = -1; dyb <= 1; dyb++) {
                int Y = by + dyb;
                if (Y < 0 || Y >= NBX) continue;
                int row = (Z * NBX + Y) * NBX;
                unsigned st = binStart[row + x0];
                unsigned en = binStart[row + x1] + binCnt[row + x1];
                for (unsigned p = st; p < en; p++) {
                    int a = binPts[p];
                    if (a < ci) {
                        float d2 = dist2(px, py, pz, cx[a], cy[a], cz[a]);
                        if (d2 < dd && nc < NNCAP)
                            loc[nc++] = (unsigned short)a;
                    }
                }
            }
        }
        g_nbrCnt[prob * 2048 + ci] = (unsigned char)nc;
        unsigned short* dst = g_nbr + (prob * 2048 + ci) * NNCAP;
        for (int k2 = 0; k2 < nc; k2++) dst[k2] = loc[k2];
    }
}

// ---------------------------------------------------------------------------
// Kernel C2b (16 blocks): load lists -> barrier-free wave NMS -> keep masks
//   + kept compact lists -> g_k*
// ---------------------------------------------------------------------------
__global__ void __launch_bounds__(1024) k_resolve(float* __restrict__ out)
{
    extern __shared__ unsigned char sm[];
    float* cx = (float*)sm;                                      // 8KB
    float* cy = (float*)(sm + 8 * 1024);
    float* cz = (float*)(sm + 16 * 1024);
    unsigned short* spos = (unsigned short*)(sm + 24 * 1024);    // 4KB
    unsigned char* fullk = (unsigned char*)(sm + 28 * 1024);     // 4KB
    unsigned short* nbr = (unsigned short*)(sm + 32 * 1024);     // 64KB
    unsigned char* nbrCnt = (unsigned char*)(sm + 96 * 1024);    // 2KB
    unsigned char* state = (unsigned char*)(sm + 98 * 1024);     // 2KB

    __shared__ int wsum[32];

    const int tid = threadIdx.x;
    const int prob = blockIdx.x;
    const int t = prob >> 3;
    const int be = prob & 7;
    const int b = be >> 1;
    const int e = be & 1;

    const int c0 = min(g_vcnt[prob * 2], MAXV);
    const int c1 = g_vcnt[prob * 2 + 1];
    const int m = min(c0 + c1, MAXV);
    const int gb = prob * 4096;

    for (int i = tid; i < c0; i += NTH) {
        cx[i] = g_vx[gb + i]; cy[i] = g_vy[gb + i]; cz[i] = g_vz[gb + i];
        spos[i] = g_vs[gb + i];
    }
    for (int i = tid; i < m - c0; i += NTH) {
        cx[c0 + i] = g_vx[gb + 2048 + i];
        cy[c0 + i] = g_vy[gb + 2048 + i];
        cz[c0 + i] = g_vz[gb + 2048 + i];
        spos[c0 + i] = g_vs[gb + 2048 + i];
    }
    {
        const unsigned int* src = (const unsigned int*)(g_nbr + prob * 2048 * NNCAP);
        unsigned int* dst = (unsigned int*)nbr;
        int words = m * (NNCAP / 2);
        for (int i = tid; i < words; i += NTH) dst[i] = src[i];
    }
    for (int i = tid; i < m; i += NTH) {
        unsigned char nc = g_nbrCnt[prob * 2048 + i];
        nbrCnt[i] = nc;
        state[i] = (nc == 0) ? (unsigned char)1 : (unsigned char)0;
    }
    for (int q = 0; q < 4; q++) fullk[tid * 4 + q] = 0;
    __syncthreads();

    // ---- barrier-free wave NMS fixpoint (confluent, monotone) ----
    {
        volatile unsigned char* vst = (volatile unsigned char*)state;
        int p0 = tid, p1 = tid + NTH;
        bool d0 = (p0 >= m) || (state[p0] != 0);
        bool d1 = (p1 >= m) || (state[p1] != 0);
        while (!(d0 && d1)) {
            if (!d0) {
                int nc = nbrCnt[p0];
                const unsigned short* nl = nbr + p0 * NNCAP;
                bool anyK = false, allS = true;
                for (int k2 = 0; k2 < nc; k2++) {
                    unsigned char s2 = vst[nl[k2]];
                    if (s2 == 1) { anyK = true; break; }
                    allS &= (s2 == 2);
                }
                if (anyK) { vst[p0] = 2; d0 = true; }
                else if (allS) { vst[p0] = 1; d0 = true; }
            }
            if (!d1) {
                int nc = nbrCnt[p1];
                const unsigned short* nl = nbr + p1 * NNCAP;
                bool anyK = false, allS = true;
                for (int k2 = 0; k2 < nc; k2++) {
                    unsigned char s2 = vst[nl[k2]];
                    if (s2 == 1) { anyK = true; break; }
                    allS &= (s2 == 2);
                }
                if (anyK) { vst[p1] = 2; d1 = true; }
                else if (allS) { vst[p1] = 1; d1 = true; }
            }
        }
    }
    __syncthreads();

    for (int ci = tid; ci < m; ci += NTH)
        fullk[spos[ci]] = (state[ci] == 1) ? 1 : 0;

    {
        int base2 = tid * 2;
        int k0 = (base2 < m) ? (state[base2] == 1) : 0;
        int k1 = (base2 + 1 < m) ? (state[base2 + 1] == 1) : 0;
        int ex2 = blockScanExcl(k0 + k1, wsum, tid);
        int kc = wsum[31];
        int kb2 = prob * 2048;
        if (k0) {
            g_kx[kb2 + ex2] = cx[base2]; g_ky[kb2 + ex2] = cy[base2];
            g_kz[kb2 + ex2] = cz[base2]; g_kpos[kb2 + ex2] = spos[base2];
            ex2++;
        }
        if (k1) {
            g_kx[kb2 + ex2] = cx[base2 + 1]; g_ky[kb2 + ex2] = cy[base2 + 1];
            g_kz[kb2 + ex2] = cz[base2 + 1]; g_kpos[kb2 + ex2] = spos[base2 + 1];
        }
        if (tid == 0) g_kcnt[prob] = kc;
    }

    int kb = (t ? OFF_KT : OFF_KP) + (b * 2 + e) * 4096;
    for (int q = 0; q < 4; q++) {
        int s = tid * 4 + q;
        out[kb + s] = (float)fullk[s];
    }
}

// ---------------------------------------------------------------------------
// Kernel D1 (32 blocks, 4/problem): bin kept targets + candidate lists for
//   one quarter of kept preds -> g_cand / g_candCnt
// ---------------------------------------------------------------------------
__global__ void __launch_bounds__(1024) k_mbuild()
{
    extern __shared__ unsigned char sm[];
    float* ctx = (float*)sm;                                     // 8KB
    float* cty = (float*)(sm + 8 * 1024);
    float* ctz = (float*)(sm + 16 * 1024);
    unsigned int* binCnt = (unsigned int*)(sm + 24 * 1024);      // 32KB
    unsigned int* binStart = (unsigned int*)(sm + 56 * 1024);    // 32KB
    unsigned short* binPts = (unsigned short*)(sm + 88 * 1024);  // 4KB

    __shared__ int wsum[32];

    const int tid = threadIdx.x;
    const int bi = blockIdx.x;
    const int be = bi >> 2;          // 0..7
    const int quarter = bi & 3;
    const int e = be & 1;
    const float de = (e == 0) ? (float)(0.74 * 1.4) : (float)(0.528 * 1.4);
    const float dd = __fmul_rn(de, de);
    const float cellXY = fmaxf(de, 1.02f);
    const float invXY = 1.0f / cellXY;
    const float invZ = 1.0f / 1.3125f;

    const int pP = be, pT = 8 + be;
    const int KP = min(g_kcnt[pP], 2048);
    const int KT = min(g_kcnt[pT], 2048);

    // load kept targets
    for (int i = tid; i < KT; i += NTH) {
        ctx[i] = g_kx[pT * 2048 + i];
        cty[i] = g_ky[pT * 2048 + i];
        ctz[i] = g_kz[pT * 2048 + i];
    }
    for (int i = tid; i < NBX * NBX * NBZ; i += NTH) binCnt[i] = 0;
    __syncthreads();

    // bins over targets
    for (int ci = tid; ci < KT; ci += NTH) {
        int bx, by, bz;
        binCoords(ctx[ci], cty[ci], ctz[ci], invXY, invZ, bx, by, bz);
        atomicAdd(&binCnt[(bz * NBX + by) * NBX + bx], 1u);
    }
    __syncthreads();
    {
        int base8 = tid * 8;
        int loc[8]; int s = 0;
        for (int k2 = 0; k2 < 8; k2++) { loc[k2] = s; s += (int)binCnt[base8 + k2]; }
        int ex = blockScanExcl(s, wsum, tid);
        for (int k2 = 0; k2 < 8; k2++) binStart[base8 + k2] = (unsigned)(ex + loc[k2]);
    }
    __syncthreads();
    for (int i = tid; i < NBX * NBX * NBZ; i += NTH) binCnt[i] = 0;
    __syncthreads();
    for (int ci = tid; ci < KT; ci += NTH) {
        int bx, by, bz;
        binCoords(ctx[ci], cty[ci], ctz[ci], invXY, invZ, bx, by, bz);
        int bb = (bz * NBX + by) * NBX + bx;
        unsigned off = atomicAdd(&binCnt[bb], 1u);
        binPts[binStart[bb] + off] = (unsigned short)ci;
    }
    __syncthreads();

    // candidate lists for our quarter of preds (coords from L2-hot g_k*)
    const int seg = (KP + 3) >> 2;
    const int st0 = quarter * seg;
    const int en0 = min(st0 + seg, KP);
    for (int ci = st0 + tid; ci < en0; ci += NTH) {
        float px = g_kx[pP * 2048 + ci];
        float py = g_ky[pP * 2048 + ci];
        float pz = g_kz[pP * 2048 + ci];
        int bx, by, bz;
        binCoords(px, py, pz, invXY, invZ, bx, by, bz);
        int x0 = bx > 0 ? bx - 1 : 0;
        int x1 = bx < NBX - 1 ? bx + 1 : NBX - 1;
        unsigned short cl[CAP];
        int nc = 0;
        #pragma unroll
        for (int dzb = -1; dzb <= 1; dzb++) {
            int Z = bz + dzb;
            if (Z < 0 || Z >= NBZ) continue;
            #pragma unroll
            for (int dyb = -1; dyb <= 1; dyb++) {
                int Y = by + dyb;
                if (Y < 0 || Y >= NBX) continue;
                int row = (Z * NBX + Y) * NBX;
                unsigned st = binStart[row + x0];
                unsigned en = binStart[row + x1] + binCnt[row + x1];
                for (unsigned p = st; p < en; p++) {
                    int a = binPts[p];
                    float d2 = dist2(px, py, pz, ctx[a], cty[a], ctz[a]);
                    if (d2 < dd) {
                        if (nc < CAP) {
                            int k2 = nc;
                            while (k2 > 0 && cl[k2 - 1] > a) { cl[k2] = cl[k2 - 1]; k2--; }
                            cl[k2] = (unsigned short)a;
                            nc++;
                        } else if (a < cl[CAP - 1]) {
                            int k2 = CAP - 1;
                            while (k2 > 0 && cl[k2 - 1] > a) { cl[k2] = cl[k2 - 1]; k2--; }
                            cl[k2] = (unsigned short)a;
                        }
                    }
                }
            }
        }
        g_candCnt[be * 2048 + ci] = (unsigned char)nc;
        unsigned short* dst = g_cand + (be * 2048 + ci) * CAP;
        for (int k2 = 0; k2 < nc; k2++) dst[k2] = cl[k2];
    }
}

// ---------------------------------------------------------------------------
// Kernel D2 (8 blocks): load candidate lists -> active-list wave matching
//   -> tp/fp/fn
// ---------------------------------------------------------------------------
__global__ void __launch_bounds__(1024) k_mresolve(float* __restrict__ out)
{
    extern __shared__ unsigned char sm[];
    unsigned short* cand = (unsigned short*)sm;                  // 48KB
    unsigned char* candCnt = (unsigned char*)(sm + 48 * 1024);   // 2KB
    unsigned short* ppos = (unsigned short*)(sm + 50 * 1024);    // 4KB
    unsigned short* tpos = (unsigned short*)(sm + 54 * 1024);    // 4KB
    unsigned int* minIdx = (unsigned int*)(sm + 58 * 1024);      // 8KB
    unsigned short* actA = (unsigned short*)(sm + 66 * 1024);    // 4KB
    unsigned short* actB = (unsigned short*)(sm + 70 * 1024);    // 4KB
    unsigned char* tpF = (unsigned char*)(sm + 74 * 1024);       // 4KB
    unsigned char* mtF = (unsigned char*)(sm + 78 * 1024);       // 4KB
    unsigned int* taken = (unsigned int*)(sm + 82 * 1024);       // 256B

    __shared__ int nact, nNext;

    const int tid = threadIdx.x;
    const int be = blockIdx.x;
    const int b = be >> 1, e = be & 1;

    const int kpBase = OFF_KP + (b * 2 + e) * 4096;
    const int ktBase = OFF_KT + (b * 2 + e) * 4096;
    const int pP = be, pT = 8 + be;

    const int KP = min(g_kcnt[pP], 2048);
    const int KT = min(g_kcnt[pT], 2048);

    // coalesced u32 copy of candidate lists (CAP=12 u16 = 6 u32 per pred)
    {
        const unsigned int* src = (const unsigned int*)(g_cand + be * 2048 * CAP);
        unsigned int* dst = (unsigned int*)cand;
        int words = KP * (CAP / 2);
        for (int i = tid; i < words; i += NTH) dst[i] = src[i];
    }
    for (int i = tid; i < KP; i += NTH) {
        candCnt[i] = g_candCnt[be * 2048 + i];
        ppos[i] = g_kpos[pP * 2048 + i];
    }
    for (int i = tid; i < KT; i += NTH) tpos[i] = g_kpos[pT * 2048 + i];
    if (tid < 64) taken[tid] = 0u;
    if (tid == 0) { nact = 0; nNext = 0; }
    for (int q = 0; q < 4; q++) { tpF[tid * 4 + q] = 0; mtF[tid * 4 + q] = 0; }
    __syncthreads();

    // initial active list
    for (int i = tid; i < KP; i += NTH) {
        if (candCnt[i] > 0) {
            int p = atomicAdd(&nact, 1);
            actA[p] = (unsigned short)i;
        }
    }
    int parity = 0;

    // active-list wave resolution (exact sequential semantics)
    while (true) {
        __syncthreads();
        int na = nact;
        if (na <= 0) break;
        const unsigned short* A = parity ? actB : actA;
        unsigned short* Bn = parity ? actA : actB;

        for (int idx = tid; idx < na; idx += NTH) {
            int i = A[idx];
            int nc = candCnt[i];
            const unsigned short* cl = cand + i * CAP;
            for (int k2 = 0; k2 < nc; k2++) minIdx[cl[k2]] = 0x7FFFFFFFu;
        }
        if (tid == 0) nNext = 0;
        __syncthreads();
        for (int idx = tid; idx < na; idx += NTH) {
            int i = A[idx];
            int nc = candCnt[i];
            const unsigned short* cl = cand + i * CAP;
            for (int k2 = 0; k2 < nc; k2++)
                atomicMin(&minIdx[cl[k2]], (unsigned)i);
        }
        __syncthreads();
        for (int idx = tid; idx < na; idx += NTH) {
            int i = A[idx];
            int nc = candCnt[i];
            const unsigned short* cl = cand + i * CAP;
            bool ok = true;
            for (int k2 = 0; k2 < nc; k2++)
                if (minIdx[cl[k2]] < (unsigned)i) { ok = false; break; }
            if (ok) {
                for (int k2 = 0; k2 < nc; k2++) {
                    int j = cl[k2];
                    if (!((taken[j >> 5] >> (j & 31)) & 1u)) {
                        atomicOr(&taken[j >> 5], 1u << (j & 31));
                        tpF[ppos[i]] = 1;
                        mtF[tpos[j]] = 1;
                        break;
                    }
                }
            } else {
                int p = atomicAdd(&nNext, 1);
                Bn[p] = (unsigned short)i;
            }
        }
        __syncthreads();
        if (tid == 0) nact = nNext;
        parity ^= 1;
    }

    // write tp/fp/fn
    const int tpB = OFF_TP + (b * 2 + e) * 4096;
    const int fpB = OFF_FP + (b * 2 + e) * 4096;
    const int fnB = OFF_FN + (b * 2 + e) * 4096;
    for (int q = 0; q < 4; q++) {
        int s = tid * 4 + q;
        int tp = tpF[s];
        int kp = (out[kpBase + s] > 0.5f) ? 1 : 0;
        int kt = (out[ktBase + s] > 0.5f) ? 1 : 0;
        out[tpB + s] = (float)tp;
        out[fpB + s] = (kp && !tp) ? 1.0f : 0.0f;
        out[fnB + s] = (kt && !mtF[s]) ? 1.0f : 0.0f;
    }
}

// ---------------------------------------------------------------------------
extern "C" void kernel_launch(void* const* d_in, const int* in_sizes, int n_in,
                              void* d_out, int out_size)
{
    const float* pred = (const float*)d_in[0];
    const float* targ = (const float*)d_in[1];
    float* out = (float*)d_out;

    cudaFuncSetAttribute(k_build, cudaFuncAttributeMaxDynamicSharedMemorySize, 96 * 1024);
    cudaFuncSetAttribute(k_resolve, cudaFuncAttributeMaxDynamicSharedMemorySize, 104 * 1024);
    cudaFuncSetAttribute(k_mbuild, cudaFuncAttributeMaxDynamicSharedMemorySize, 96 * 1024);
    cudaFuncSetAttribute(k_mresolve, cudaFuncAttributeMaxDynamicSharedMemorySize, 88 * 1024);

    k_sortA<<<64, NTH, 8 * 1024>>>(pred, targ);
    k_sortB<<<32, NTH, 16 * 1024>>>();
    k_coords<<<32, NTH, 32 * 1024>>>(pred, targ, out);
    k_build<<<64, NTH, 92 * 1024>>>();
    k_resolve<<<16, NTH, 104 * 1024>>>(out);
    k_mbuild<<<32, NTH, 92 * 1024>>>();
    k_mresolve<<<8, NTH, 84 * 1024>>>(out);
}